// round 9
// baseline (speedup 1.0000x reference)
#include <cuda_runtime.h>
#include <cuda_bf16.h>
#include <math.h>
#include <stdint.h>

#define NB   64
#define NT   256
#define EMBD 512
#define VOCAB 32000
#define RNN  1024
#define Z4   4096
#define HIDN 128
#define NLAB 4

// Column permutation: original n = gate*1024 + j  ->  col' = j*4 + gate.

// ---------------- static device scratch ----------------------------------
__device__ float g_XW[(size_t)NT * NB * Z4];            // emb[x] @ W  (col' layout)
__device__ __nv_bfloat16 g_UThi[(size_t)Z4 * RNN];      // U^T hi, [col'][k]
__device__ __nv_bfloat16 g_UTlo[(size_t)Z4 * RNN];
__device__ __nv_bfloat16 g_WThi[(size_t)Z4 * EMBD];
__device__ __nv_bfloat16 g_WTlo[(size_t)Z4 * EMBD];
__device__ __nv_bfloat16 g_Ehi[(size_t)VOCAB * EMBD];
__device__ __nv_bfloat16 g_Elo[(size_t)VOCAB * EMBD];
__device__ __nv_bfloat16 g_H2[2][64 * 2048];            // ping-pong: row b = [hi(1024) | lo(1024)]
__device__ float g_c[NB * RNN];
__device__ float g_pooled[NB * RNN];
__device__ int   g_active[NT];
__device__ unsigned g_arrive;
__device__ int   g_release;

// ---------------- helpers --------------------------------------------------
__device__ __forceinline__ uint32_t smem_u32(const void* p) {
    return (uint32_t)__cvta_generic_to_shared(p);
}
__device__ __forceinline__ void cp_async16(uint32_t smem_dst, const void* gsrc) {
    asm volatile("cp.async.cg.shared.global [%0], [%1], 16;" :: "r"(smem_dst), "l"(gsrc));
}
#define CP_COMMIT() asm volatile("cp.async.commit_group;" ::: "memory")

__device__ __forceinline__ void ldsm_x4(uint32_t& r0, uint32_t& r1,
                                        uint32_t& r2, uint32_t& r3, uint32_t addr) {
    asm volatile("ldmatrix.sync.aligned.m8n8.x4.shared.b16 {%0,%1,%2,%3}, [%4];"
                 : "=r"(r0), "=r"(r1), "=r"(r2), "=r"(r3) : "r"(addr));
}
__device__ __forceinline__ void mma_bf16(float* c, uint32_t a0, uint32_t a1,
                                         uint32_t a2, uint32_t a3,
                                         uint32_t b0, uint32_t b1) {
    asm volatile("mma.sync.aligned.m16n8k16.row.col.f32.bf16.bf16.f32 "
                 "{%0,%1,%2,%3}, {%4,%5,%6,%7}, {%8,%9}, {%0,%1,%2,%3};"
                 : "+f"(c[0]), "+f"(c[1]), "+f"(c[2]), "+f"(c[3])
                 : "r"(a0), "r"(a1), "r"(a2), "r"(a3), "r"(b0), "r"(b1));
}

// ---------------- prep -----------------------------------------------------
__global__ void prep_kernel(const int* __restrict__ x) {
    int t = threadIdx.x;
    if (t < NT) {
        int act = 0;
        for (int b = 0; b < NB; b++) act |= (x[b * NT + t] != 0);
        g_active[t] = act;
    }
    if (t == 0) { g_arrive = 0; g_release = 0; }
}

__global__ void zero_kernel() {
    int i = blockIdx.x * blockDim.x + threadIdx.x;   // 512*256 = 131072
    if (i < NB * RNN) { g_c[i] = 0.f; g_pooled[i] = 0.f; }
    ((uint32_t*)g_H2)[i] = 0u;                       // both ping-pong buffers
}

// ---------------- emb split ------------------------------------------------
__global__ __launch_bounds__(256) void esplit_kernel(const float* __restrict__ emb) {
    size_t i = (size_t)blockIdx.x * 256 + threadIdx.x;
    float v = emb[i];
    __nv_bfloat16 hi = __float2bfloat16(v);
    g_Ehi[i] = hi;
    g_Elo[i] = __float2bfloat16(v - __bfloat162float(hi));
}

// ---------------- transpose+split+permute: U and W -------------------------
__device__ __forceinline__ int permute_col(int n) {
    return (n & 1023) * 4 + (n >> 10);
}

__global__ __launch_bounds__(256) void upack_kernel(const float* __restrict__ U) {
    __shared__ float tile[64][65];
    const int k0 = blockIdx.x * 64;
    const int n0 = blockIdx.y * 64;
    const int tid = threadIdx.x;
    #pragma unroll
    for (int it = 0; it < 16; it++) {
        int r = it * 4 + (tid >> 6);
        int c = tid & 63;
        tile[r][c] = U[(size_t)(k0 + r) * Z4 + n0 + c];
    }
    __syncthreads();
    #pragma unroll
    for (int it = 0; it < 16; it++) {
        int n = it * 4 + (tid >> 6);
        int k = tid & 63;
        float v = tile[k][n];
        __nv_bfloat16 hi = __float2bfloat16(v);
        const int np = permute_col(n0 + n);
        g_UThi[(size_t)np * RNN + k0 + k] = hi;
        g_UTlo[(size_t)np * RNN + k0 + k] =
            __float2bfloat16(v - __bfloat162float(hi));
    }
}

__global__ __launch_bounds__(256) void wpack_kernel(const float* __restrict__ W) {
    __shared__ float tile[64][65];
    const int k0 = blockIdx.x * 64;
    const int n0 = blockIdx.y * 64;
    const int tid = threadIdx.x;
    #pragma unroll
    for (int it = 0; it < 16; it++) {
        int r = it * 4 + (tid >> 6);
        int c = tid & 63;
        tile[r][c] = W[(size_t)(k0 + r) * Z4 + n0 + c];
    }
    __syncthreads();
    #pragma unroll
    for (int it = 0; it < 16; it++) {
        int n = it * 4 + (tid >> 6);
        int k = tid & 63;
        float v = tile[k][n];
        __nv_bfloat16 hi = __float2bfloat16(v);
        const int np = permute_col(n0 + n);
        g_WThi[(size_t)np * EMBD + k0 + k] = hi;
        g_WTlo[(size_t)np * EMBD + k0 + k] =
            __float2bfloat16(v - __bfloat162float(hi));
    }
}

// ---------------- HMMA input projection (unchanged) ------------------------
#define BUF_BYTES 32768
#define GEMM_SMEM (1024 + 2 * BUF_BYTES)
#define XCHUNKS 16

__global__ __launch_bounds__(256) void xw_mma_kernel(const int* __restrict__ x) {
    const int t = blockIdx.y;
    if (!g_active[t]) return;

    extern __shared__ char dyn[];
    __shared__ int idxs[64];
    const uint32_t tb = (smem_u32(dyn) + 1023u) & ~1023u;

    const int tid  = threadIdx.x;
    const int w    = tid >> 5;
    const int lane = tid & 31;
    const int n0   = blockIdx.x * 128;
    const int mw   = w >> 1;
    const int nw   = w & 1;

    if (tid < 64) idxs[tid] = x[tid * NT + t];
    __syncthreads();

    float c[2][4][2][4];
    #pragma unroll
    for (int i = 0; i < 2; i++)
        #pragma unroll
        for (int j = 0; j < 4; j++)
            #pragma unroll
            for (int h = 0; h < 2; h++)
                #pragma unroll
                for (int r = 0; r < 4; r++) c[i][j][h][r] = 0.f;

    auto load_chunk = [&](int ch, int slot) {
        const uint32_t ab = tb + slot * BUF_BYTES;
        const uint32_t bb = ab + 16384;
        const int pass = ch >> 3;
        const int kg = (ch & 7) * 64;
        const __nv_bfloat16* Bsrc =
            (pass ? g_WTlo : g_WThi) + (size_t)n0 * EMBD + kg;
        #pragma unroll
        for (int r = 0; r < 4; r++) {
            const int o   = tid + 256 * r;
            const int row = o >> 3;
            const int cb  = o & 7;
            uint32_t off = (uint32_t)(row * 128 + cb * 16);
            uint32_t sw  = off ^ ((off >> 3) & 0x70);
            const __nv_bfloat16* asrc =
                (row < 64) ? (g_Ehi + (size_t)idxs[row] * EMBD + kg + cb * 8)
                           : (g_Elo + (size_t)idxs[row - 64] * EMBD + kg + cb * 8);
            cp_async16(ab + sw, asrc);
            cp_async16(bb + sw, Bsrc + (size_t)row * EMBD + cb * 8);
        }
        CP_COMMIT();
    };

    load_chunk(0, 0);

    const int lrow = ((lane >> 3) & 1) * 8 + (lane & 7);
    const int lcolb = (lane >> 4) * 16;

    for (int ch = 0; ch < XCHUNKS; ch++) {
        if (ch + 1 < XCHUNKS) load_chunk(ch + 1, (ch + 1) & 1);
        if (ch + 1 < XCHUNKS) asm volatile("cp.async.wait_group 1;" ::: "memory");
        else                  asm volatile("cp.async.wait_group 0;" ::: "memory");
        __syncthreads();

        const uint32_t ab = tb + (ch & 1) * BUF_BYTES;
        const uint32_t bb = ab + 16384;

        #pragma unroll
        for (int kk = 0; kk < 4; kk++) {
            uint32_t bf[4][4];
            #pragma unroll
            for (int nt = 0; nt < 4; nt++) {
                uint32_t boff = (uint32_t)((nw * 64 + nt * 16 + lrow) * 128 + kk * 32 + lcolb);
                uint32_t baddr = bb + (boff ^ ((boff >> 3) & 0x70));
                ldsm_x4(bf[nt][0], bf[nt][1], bf[nt][2], bf[nt][3], baddr);
            }
            #pragma unroll
            for (int mt = 0; mt < 2; mt++) {
                const int mbase = mt * 64 + mw * 16;
                uint32_t aoff = (uint32_t)((mbase + lrow) * 128 + kk * 32 + lcolb);
                uint32_t aaddr = ab + (aoff ^ ((aoff >> 3) & 0x70));
                uint32_t a0, a1, a2, a3;
                ldsm_x4(a0, a1, a2, a3, aaddr);
                #pragma unroll
                for (int nt = 0; nt < 4; nt++) {
                    mma_bf16(c[mt][nt][0], a0, a1, a2, a3, bf[nt][0], bf[nt][2]);
                    mma_bf16(c[mt][nt][1], a0, a1, a2, a3, bf[nt][1], bf[nt][3]);
                }
            }
        }
        __syncthreads();
    }

    float* C = g_XW + (size_t)t * NB * Z4;
    #pragma unroll
    for (int nt = 0; nt < 4; nt++) {
        #pragma unroll
        for (int h = 0; h < 2; h++) {
            const int row = mw * 16 + (lane >> 2);
            const int col = n0 + nw * 64 + nt * 16 + h * 8 + (lane & 3) * 2;
            float2 v01 = make_float2(c[0][nt][h][0] + c[1][nt][h][0],
                                     c[0][nt][h][1] + c[1][nt][h][1]);
            float2 v23 = make_float2(c[0][nt][h][2] + c[1][nt][h][2],
                                     c[0][nt][h][3] + c[1][nt][h][3]);
            *reinterpret_cast<float2*>(C + (size_t)row * Z4 + col) = v01;
            *reinterpret_cast<float2*>(C + (size_t)(row + 8) * Z4 + col) = v23;
        }
    }
}

// ---------------- persistent recurrence (3-term split, 1 barrier) ----------
// 128 blocks x 256 thr. Block owns 32 col' columns (= 8 hidden units, 4 gates),
// all 64 batches. B (Uhi+Ulo slices, 128KB) resident in smem; A streamed.
// z = h_hi@U_hi + h_hi@U_lo + h_lo@U_hi (h_lo@U_lo dropped, ~2^-18).
#define A_OFF   131072
#define Z_OFF   (131072 + 16384)
#define RNN_SMEM (1024 + 131072 + 16384 + 64 * 34 * 4)

__global__ __launch_bounds__(256, 1) void rnn_persist(const int* __restrict__ x,
                                                      const float* __restrict__ bias) {
    extern __shared__ char dyn[];
    __shared__ int sact[NT];
    __shared__ float sbias[32];
    const uint32_t dynb = smem_u32(dyn);
    const uint32_t tb   = (dynb + 1023u) & ~1023u;   // B: 32 chunks x 4KB
    const uint32_t ab0  = tb + A_OFF;                // A: 2 x 8KB
    float* zbuf = (float*)(dyn + (tb - dynb) + Z_OFF);  // [64][34]

    const int tid  = threadIdx.x;
    const int w    = tid >> 5;
    const int lane = tid & 31;
    const int bid  = blockIdx.x;
    const int n0   = bid * 32;     // col' slice
    const int j0   = bid * 8;      // hidden units owned
    const int mw   = w >> 1;       // 0..3
    const int nw   = w & 1;        // 0..1

    sact[tid] = g_active[tid];
    if (tid < 32) sbias[tid] = bias[(tid & 3) * RNN + j0 + (tid >> 2)];

    // ---- load resident B: chunks 0..15 = Uhi, 16..31 = Ulo ----
    #pragma unroll
    for (int r = 0; r < 32; r++) {
        const int o  = tid + 256 * r;    // 0..8191
        const int ch = o >> 8;           // 0..31
        const int n  = (o >> 3) & 31;
        const int cb = o & 7;
        uint32_t off = (uint32_t)(n * 128 + cb * 16);
        uint32_t sw  = off ^ ((off >> 3) & 0x70);
        const __nv_bfloat16* src =
            (ch < 16 ? g_UThi + (size_t)(n0 + n) * RNN + ch * 64
                     : g_UTlo + (size_t)(n0 + n) * RNN + (ch - 16) * 64) + cb * 8;
        cp_async16(tb + ch * 4096 + sw, src);
    }
    CP_COMMIT();
    asm volatile("cp.async.wait_group 0;" ::: "memory");
    __syncthreads();

    const int lrow = ((lane >> 3) & 1) * 8 + (lane & 7);
    const int lcolb = (lane >> 4) * 16;

    int epoch = 0;
    int rb = 0;

    for (int t = 0; t < NT; t++) {
        if (!sact[t]) continue;
        const __nv_bfloat16* Asrc = g_H2[rb];   // [64][2048]

        float c[2][4];
        #pragma unroll
        for (int j = 0; j < 2; j++)
            #pragma unroll
            for (int r = 0; r < 4; r++) c[j][r] = 0.f;

        // A chunk ac: 0..15 = h_hi chunks, 16..31 = h_lo chunks
        auto load_a = [&](int ac, int slot) {
            const uint32_t ab = ab0 + slot * 8192;
            const int colbase = (ac < 16) ? ac * 64 : 1024 + (ac - 16) * 64;
            #pragma unroll
            for (int r = 0; r < 2; r++) {
                const int o   = tid + 256 * r;   // 0..511
                const int row = o >> 3;          // 0..63
                const int cb  = o & 7;
                uint32_t off = (uint32_t)(row * 128 + cb * 16);
                uint32_t sw  = off ^ ((off >> 3) & 0x70);
                cp_async16(ab + sw, Asrc + (size_t)row * 2048 + colbase + cb * 8);
            }
            CP_COMMIT();
        };

        load_a(0, 0);

        for (int ac = 0; ac < 32; ac++) {
            if (ac + 1 < 32) load_a(ac + 1, (ac + 1) & 1);
            if (ac + 1 < 32) asm volatile("cp.async.wait_group 1;" ::: "memory");
            else             asm volatile("cp.async.wait_group 0;" ::: "memory");
            __syncthreads();

            const uint32_t ab = ab0 + (ac & 1) * 8192;

            #pragma unroll
            for (int kk = 0; kk < 4; kk++) {
                uint32_t aoff = (uint32_t)((mw * 16 + lrow) * 128 + kk * 32 + lcolb);
                uint32_t aaddr = ab + (aoff ^ ((aoff >> 3) & 0x70));
                uint32_t a0, a1, a2, a3;
                ldsm_x4(a0, a1, a2, a3, aaddr);

                uint32_t boff = (uint32_t)((nw * 16 + lrow) * 128 + kk * 32 + lcolb);
                uint32_t bsw  = boff ^ ((boff >> 3) & 0x70);

                if (ac < 16) {
                    // h_hi x U_hi  and  h_hi x U_lo
                    uint32_t b0, b1, b2, b3;
                    ldsm_x4(b0, b1, b2, b3, tb + ac * 4096 + bsw);
                    mma_bf16(c[0], a0, a1, a2, a3, b0, b2);
                    mma_bf16(c[1], a0, a1, a2, a3, b1, b3);
                    uint32_t d0, d1, d2, d3;
                    ldsm_x4(d0, d1, d2, d3, tb + (16 + ac) * 4096 + bsw);
                    mma_bf16(c[0], a0, a1, a2, a3, d0, d2);
                    mma_bf16(c[1], a0, a1, a2, a3, d1, d3);
                } else {
                    // h_lo x U_hi
                    uint32_t b0, b1, b2, b3;
                    ldsm_x4(b0, b1, b2, b3, tb + (ac - 16) * 4096 + bsw);
                    mma_bf16(c[0], a0, a1, a2, a3, b0, b2);
                    mma_bf16(c[1], a0, a1, a2, a3, b1, b3);
                }
            }
            __syncthreads();
        }

        // epilogue -> smem zbuf [64][34]
        #pragma unroll
        for (int nt = 0; nt < 2; nt++) {
            const int row = mw * 16 + (lane >> 2);
            const int col = nw * 16 + nt * 8 + (lane & 3) * 2;
            zbuf[row * 34 + col]           = c[nt][0];
            zbuf[row * 34 + col + 1]       = c[nt][1];
            zbuf[(row + 8) * 34 + col]     = c[nt][2];
            zbuf[(row + 8) * 34 + col + 1] = c[nt][3];
        }
        __syncthreads();

        // block-local cell update: 512 cells (8 units x 64 batches)
        __nv_bfloat16* hw = g_H2[rb ^ 1];
        const __nv_bfloat16* hr = g_H2[rb];
        #pragma unroll
        for (int r = 0; r < 2; r++) {
            const int cell = r * 256 + tid;      // 0..511
            const int b  = cell >> 3;            // 0..63
            const int jl = cell & 7;             // 0..7
            const int j  = j0 + jl;

            float4 xw4 = *reinterpret_cast<const float4*>(
                g_XW + ((size_t)t * NB + b) * Z4 + (size_t)j * 4);
            const float zi = xw4.x + zbuf[b * 34 + jl * 4 + 0] + sbias[jl * 4 + 0];
            const float zf = xw4.y + zbuf[b * 34 + jl * 4 + 1] + sbias[jl * 4 + 1];
            const float zg = xw4.z + zbuf[b * 34 + jl * 4 + 2] + sbias[jl * 4 + 2];
            const float zo = xw4.w + zbuf[b * 34 + jl * 4 + 3] + sbias[jl * 4 + 3];

            const float si = 1.f / (1.f + expf(-zi));
            const float sf = 1.f / (1.f + expf(-zf));
            const float so = 1.f / (1.f + expf(-zo));
            const int gi = b * RNN + j;
            const float cn = sf * g_c[gi] + si * tanhf(zg);
            const float hn = so * tanhf(cn);
            const int xv = x[b * NT + t];
            if (xv != 0) {
                g_c[gi] = cn;
                __nv_bfloat16 hi = __float2bfloat16(hn);
                hw[b * 2048 + j] = hi;
                hw[b * 2048 + 1024 + j] = __float2bfloat16(hn - __bfloat162float(hi));
            } else {
                hw[b * 2048 + j] = hr[b * 2048 + j];
                hw[b * 2048 + 1024 + j] = hr[b * 2048 + 1024 + j];
            }
            if (xv == 2) g_pooled[gi] += hn;
        }

        // ---- single grid barrier ----
        epoch++;
        __threadfence();
        __syncthreads();
        if (tid == 0) {
            unsigned old = atomicAdd(&g_arrive, 1u);
            if (old == 127u) {
                g_arrive = 0;
                asm volatile("st.release.gpu.global.s32 [%0], %1;"
                             :: "l"(&g_release), "r"(epoch) : "memory");
            } else {
                int v;
                do {
                    asm volatile("ld.acquire.gpu.global.s32 %0, [%1];"
                                 : "=r"(v) : "l"(&g_release) : "memory");
                } while (v < epoch);
            }
        }
        __syncthreads();
        __threadfence();

        rb ^= 1;
    }
}

// ---------------- head -----------------------------------------------------
__global__ __launch_bounds__(128) void head_kernel(const float* __restrict__ W1,
                                                   const float* __restrict__ b1,
                                                   const float* __restrict__ W2,
                                                   const float* __restrict__ b2,
                                                   const float* __restrict__ Wc,
                                                   const float* __restrict__ bc,
                                                   float* __restrict__ out) {
    const int b = blockIdx.x;
    const int tid = threadIdx.x;
    __shared__ float sp[RNN];
    __shared__ float h1s[HIDN];
    __shared__ float h2s[HIDN];
    __shared__ float lg[NLAB];

    for (int k = tid; k < RNN; k += 128) sp[k] = g_pooled[(size_t)b * RNN + k];
    __syncthreads();

    float a = b1[tid];
    for (int k = 0; k < RNN; k++) a += sp[k] * W1[(size_t)k * HIDN + tid];
    h1s[tid] = fmaxf(a, 0.f);
    __syncthreads();

    float a2 = b2[tid];
    for (int k = 0; k < HIDN; k++) a2 += h1s[k] * W2[(size_t)k * HIDN + tid];
    h2s[tid] = fmaxf(a2, 0.f);
    __syncthreads();

    if (tid < NLAB) {
        float l = bc[tid];
        for (int k = 0; k < HIDN; k++) l += h2s[k] * Wc[(size_t)k * NLAB + tid];
        lg[tid] = l;
    }
    __syncthreads();
    if (tid == 0) {
        const float mx = fmaxf(fmaxf(lg[0], lg[1]), fmaxf(lg[2], lg[3]));
        const float e0 = expf(lg[0] - mx), e1 = expf(lg[1] - mx);
        const float e2 = expf(lg[2] - mx), e3 = expf(lg[3] - mx);
        const float sden = e0 + e1 + e2 + e3;
        out[b * 4 + 0] = e0 / sden; out[b * 4 + 1] = e1 / sden;
        out[b * 4 + 2] = e2 / sden; out[b * 4 + 3] = e3 / sden;
    }
}

// ---------------- launcher -------------------------------------------------
extern "C" void kernel_launch(void* const* d_in, const int* in_sizes, int n_in,
                              void* d_out, int out_size) {
    const int*   x    = (const int*)d_in[0];
    const float* emb  = (const float*)d_in[1];
    const float* W    = (const float*)d_in[2];
    const float* U    = (const float*)d_in[3];
    const float* bias = (const float*)d_in[4];
    const float* W1   = (const float*)d_in[5];
    const float* b1   = (const float*)d_in[6];
    const float* W2   = (const float*)d_in[7];
    const float* b2   = (const float*)d_in[8];
    const float* Wc   = (const float*)d_in[9];
    const float* bc   = (const float*)d_in[10];
    float* out = (float*)d_out;

    cudaFuncSetAttribute(xw_mma_kernel, cudaFuncAttributeMaxDynamicSharedMemorySize, GEMM_SMEM);
    cudaFuncSetAttribute(rnn_persist, cudaFuncAttributeMaxDynamicSharedMemorySize, RNN_SMEM);

    prep_kernel<<<1, 256>>>(x);
    zero_kernel<<<512, 256>>>();
    esplit_kernel<<<(VOCAB * EMBD) / 256, 256>>>(emb);
    upack_kernel<<<dim3(RNN / 64, Z4 / 64), 256>>>(U);
    wpack_kernel<<<dim3(EMBD / 64, Z4 / 64), 256>>>(W);
    xw_mma_kernel<<<dim3(32, NT), 256, GEMM_SMEM>>>(x);
    rnn_persist<<<128, 256, RNN_SMEM>>>(x, bias);
    head_kernel<<<NB, 128>>>(W1, b1, W2, b2, Wc, bc, out);
}

// round 10
// speedup vs baseline: 1.3555x; 1.3555x over previous
#include <cuda_runtime.h>
#include <cuda_bf16.h>
#include <math.h>
#include <stdint.h>

#define NB   64
#define NT   256
#define EMBD 512
#define VOCAB 32000
#define RNN  1024
#define Z4   4096
#define HIDN 128
#define NLAB 4

// Column permutation: original n = gate*1024 + j  ->  col' = j*4 + gate.

// ---------------- static device scratch ----------------------------------
__device__ float g_XW[(size_t)NT * NB * Z4];            // emb[x] @ W  (col' layout)
__device__ __nv_bfloat16 g_UThi[(size_t)Z4 * RNN];      // U^T hi, [col'][k]
__device__ __nv_bfloat16 g_UTlo[(size_t)Z4 * RNN];
__device__ __nv_bfloat16 g_WThi[(size_t)Z4 * EMBD];
__device__ __nv_bfloat16 g_WTlo[(size_t)Z4 * EMBD];
__device__ __nv_bfloat16 g_Ehi[(size_t)VOCAB * EMBD];
__device__ __nv_bfloat16 g_Elo[(size_t)VOCAB * EMBD];
__device__ __nv_bfloat16 g_H2[2][64 * 2048];            // ping-pong: row b = [hi(1024) | lo(1024)]
__device__ float g_pooled[NB * RNN];
__device__ int   g_active[NT];
__device__ unsigned g_arrive;
__device__ int   g_release;

// ---------------- helpers --------------------------------------------------
__device__ __forceinline__ uint32_t smem_u32(const void* p) {
    return (uint32_t)__cvta_generic_to_shared(p);
}
__device__ __forceinline__ void cp_async16(uint32_t smem_dst, const void* gsrc) {
    asm volatile("cp.async.cg.shared.global [%0], [%1], 16;" :: "r"(smem_dst), "l"(gsrc));
}
#define CP_COMMIT() asm volatile("cp.async.commit_group;" ::: "memory")

__device__ __forceinline__ void ldsm_x4(uint32_t& r0, uint32_t& r1,
                                        uint32_t& r2, uint32_t& r3, uint32_t addr) {
    asm volatile("ldmatrix.sync.aligned.m8n8.x4.shared.b16 {%0,%1,%2,%3}, [%4];"
                 : "=r"(r0), "=r"(r1), "=r"(r2), "=r"(r3) : "r"(addr));
}
__device__ __forceinline__ void mma_bf16(float* c, uint32_t a0, uint32_t a1,
                                         uint32_t a2, uint32_t a3,
                                         uint32_t b0, uint32_t b1) {
    asm volatile("mma.sync.aligned.m16n8k16.row.col.f32.bf16.bf16.f32 "
                 "{%0,%1,%2,%3}, {%4,%5,%6,%7}, {%8,%9}, {%0,%1,%2,%3};"
                 : "+f"(c[0]), "+f"(c[1]), "+f"(c[2]), "+f"(c[3])
                 : "r"(a0), "r"(a1), "r"(a2), "r"(a3), "r"(b0), "r"(b1));
}

// ---------------- prep -----------------------------------------------------
__global__ void prep_kernel(const int* __restrict__ x) {
    int t = threadIdx.x;
    if (t < NT) {
        int act = 0;
        for (int b = 0; b < NB; b++) act |= (x[b * NT + t] != 0);
        g_active[t] = act;
    }
    if (t == 0) { g_arrive = 0; g_release = 0; }
}

__global__ void zero_kernel() {
    int i = blockIdx.x * blockDim.x + threadIdx.x;   // 512*256 = 131072
    ((uint32_t*)g_H2)[i] = 0u;                       // both ping-pong buffers
}

// ---------------- emb split ------------------------------------------------
__global__ __launch_bounds__(256) void esplit_kernel(const float* __restrict__ emb) {
    size_t i = (size_t)blockIdx.x * 256 + threadIdx.x;
    float v = emb[i];
    __nv_bfloat16 hi = __float2bfloat16(v);
    g_Ehi[i] = hi;
    g_Elo[i] = __float2bfloat16(v - __bfloat162float(hi));
}

// ---------------- transpose+split+permute: U and W -------------------------
__device__ __forceinline__ int permute_col(int n) {
    return (n & 1023) * 4 + (n >> 10);
}

__global__ __launch_bounds__(256) void upack_kernel(const float* __restrict__ U) {
    __shared__ float tile[64][65];
    const int k0 = blockIdx.x * 64;
    const int n0 = blockIdx.y * 64;
    const int tid = threadIdx.x;
    #pragma unroll
    for (int it = 0; it < 16; it++) {
        int r = it * 4 + (tid >> 6);
        int c = tid & 63;
        tile[r][c] = U[(size_t)(k0 + r) * Z4 + n0 + c];
    }
    __syncthreads();
    #pragma unroll
    for (int it = 0; it < 16; it++) {
        int n = it * 4 + (tid >> 6);
        int k = tid & 63;
        float v = tile[k][n];
        __nv_bfloat16 hi = __float2bfloat16(v);
        const int np = permute_col(n0 + n);
        g_UThi[(size_t)np * RNN + k0 + k] = hi;
        g_UTlo[(size_t)np * RNN + k0 + k] =
            __float2bfloat16(v - __bfloat162float(hi));
    }
}

__global__ __launch_bounds__(256) void wpack_kernel(const float* __restrict__ W) {
    __shared__ float tile[64][65];
    const int k0 = blockIdx.x * 64;
    const int n0 = blockIdx.y * 64;
    const int tid = threadIdx.x;
    #pragma unroll
    for (int it = 0; it < 16; it++) {
        int r = it * 4 + (tid >> 6);
        int c = tid & 63;
        tile[r][c] = W[(size_t)(k0 + r) * Z4 + n0 + c];
    }
    __syncthreads();
    #pragma unroll
    for (int it = 0; it < 16; it++) {
        int n = it * 4 + (tid >> 6);
        int k = tid & 63;
        float v = tile[k][n];
        __nv_bfloat16 hi = __float2bfloat16(v);
        const int np = permute_col(n0 + n);
        g_WThi[(size_t)np * EMBD + k0 + k] = hi;
        g_WTlo[(size_t)np * EMBD + k0 + k] =
            __float2bfloat16(v - __bfloat162float(hi));
    }
}

// ---------------- HMMA input projection (unchanged, known-good) ------------
#define BUF_BYTES 32768
#define GEMM_SMEM (1024 + 2 * BUF_BYTES)
#define XCHUNKS 16

__global__ __launch_bounds__(256) void xw_mma_kernel(const int* __restrict__ x) {
    const int t = blockIdx.y;
    if (!g_active[t]) return;

    extern __shared__ char dyn[];
    __shared__ int idxs[64];
    const uint32_t tb = (smem_u32(dyn) + 1023u) & ~1023u;

    const int tid  = threadIdx.x;
    const int w    = tid >> 5;
    const int lane = tid & 31;
    const int n0   = blockIdx.x * 128;
    const int mw   = w >> 1;
    const int nw   = w & 1;

    if (tid < 64) idxs[tid] = x[tid * NT + t];
    __syncthreads();

    float c[2][4][2][4];
    #pragma unroll
    for (int i = 0; i < 2; i++)
        #pragma unroll
        for (int j = 0; j < 4; j++)
            #pragma unroll
            for (int h = 0; h < 2; h++)
                #pragma unroll
                for (int r = 0; r < 4; r++) c[i][j][h][r] = 0.f;

    auto load_chunk = [&](int ch, int slot) {
        const uint32_t ab = tb + slot * BUF_BYTES;
        const uint32_t bb = ab + 16384;
        const int pass = ch >> 3;
        const int kg = (ch & 7) * 64;
        const __nv_bfloat16* Bsrc =
            (pass ? g_WTlo : g_WThi) + (size_t)n0 * EMBD + kg;
        #pragma unroll
        for (int r = 0; r < 4; r++) {
            const int o   = tid + 256 * r;
            const int row = o >> 3;
            const int cb  = o & 7;
            uint32_t off = (uint32_t)(row * 128 + cb * 16);
            uint32_t sw  = off ^ ((off >> 3) & 0x70);
            const __nv_bfloat16* asrc =
                (row < 64) ? (g_Ehi + (size_t)idxs[row] * EMBD + kg + cb * 8)
                           : (g_Elo + (size_t)idxs[row - 64] * EMBD + kg + cb * 8);
            cp_async16(ab + sw, asrc);
            cp_async16(bb + sw, Bsrc + (size_t)row * EMBD + cb * 8);
        }
        CP_COMMIT();
    };

    load_chunk(0, 0);

    const int lrow = ((lane >> 3) & 1) * 8 + (lane & 7);
    const int lcolb = (lane >> 4) * 16;

    for (int ch = 0; ch < XCHUNKS; ch++) {
        if (ch + 1 < XCHUNKS) load_chunk(ch + 1, (ch + 1) & 1);
        if (ch + 1 < XCHUNKS) asm volatile("cp.async.wait_group 1;" ::: "memory");
        else                  asm volatile("cp.async.wait_group 0;" ::: "memory");
        __syncthreads();

        const uint32_t ab = tb + (ch & 1) * BUF_BYTES;
        const uint32_t bb = ab + 16384;

        #pragma unroll
        for (int kk = 0; kk < 4; kk++) {
            uint32_t bf[4][4];
            #pragma unroll
            for (int nt = 0; nt < 4; nt++) {
                uint32_t boff = (uint32_t)((nw * 64 + nt * 16 + lrow) * 128 + kk * 32 + lcolb);
                uint32_t baddr = bb + (boff ^ ((boff >> 3) & 0x70));
                ldsm_x4(bf[nt][0], bf[nt][1], bf[nt][2], bf[nt][3], baddr);
            }
            #pragma unroll
            for (int mt = 0; mt < 2; mt++) {
                const int mbase = mt * 64 + mw * 16;
                uint32_t aoff = (uint32_t)((mbase + lrow) * 128 + kk * 32 + lcolb);
                uint32_t aaddr = ab + (aoff ^ ((aoff >> 3) & 0x70));
                uint32_t a0, a1, a2, a3;
                ldsm_x4(a0, a1, a2, a3, aaddr);
                #pragma unroll
                for (int nt = 0; nt < 4; nt++) {
                    mma_bf16(c[mt][nt][0], a0, a1, a2, a3, bf[nt][0], bf[nt][2]);
                    mma_bf16(c[mt][nt][1], a0, a1, a2, a3, bf[nt][1], bf[nt][3]);
                }
            }
        }
        __syncthreads();
    }

    float* C = g_XW + (size_t)t * NB * Z4;
    #pragma unroll
    for (int nt = 0; nt < 4; nt++) {
        #pragma unroll
        for (int h = 0; h < 2; h++) {
            const int row = mw * 16 + (lane >> 2);
            const int col = n0 + nw * 64 + nt * 16 + h * 8 + (lane & 3) * 2;
            float2 v01 = make_float2(c[0][nt][h][0] + c[1][nt][h][0],
                                     c[0][nt][h][1] + c[1][nt][h][1]);
            float2 v23 = make_float2(c[0][nt][h][2] + c[1][nt][h][2],
                                     c[0][nt][h][3] + c[1][nt][h][3]);
            *reinterpret_cast<float2*>(C + (size_t)row * Z4 + col) = v01;
            *reinterpret_cast<float2*>(C + (size_t)(row + 8) * Z4 + col) = v23;
        }
    }
}

// ---------------- persistent recurrence: exact 4-term, block-local z --------
// 128 blocks x 256 thr, 1 CTA/SM. Block owns 32 col' (= 8 hidden units).
// A = [h_hi(64); h_lo(64)] (M=128), B = resident U slice, K-stacked hi|lo:
// fold rows m and m+64 => exact h@U for this block's columns.
// Per step: GEMM -> smem z -> block-local cell (c,pooled in smem) -> 1 barrier.
#define A_BUFS   3
#define A_CHUNK  16384
#define B_BYTES  131072
#define ZB_OFF   (B_BYTES + A_BUFS * A_CHUNK)
#define CS_OFF   (ZB_OFF + 64 * 33 * 4)
#define RNN_SMEM (1024 + CS_OFF + 4096)

__global__ __launch_bounds__(256, 1) void rnn_persist(const int* __restrict__ x,
                                                      const float* __restrict__ bias) {
    extern __shared__ char dyn[];
    __shared__ int sact[NT];
    __shared__ float sbias[32];
    const uint32_t dynb = smem_u32(dyn);
    const uint32_t tb   = (dynb + 1023u) & ~1023u;   // B: 32 chunks x 4KB
    const uint32_t ab0  = tb + B_BYTES;              // A: 3 x 16KB
    char* dynal = dyn + (tb - dynb);
    float* zbuf     = (float*)(dynal + ZB_OFF);      // [64][33]
    float* cs       = (float*)(dynal + CS_OFF);      // [512]
    float* pooled_s = cs + 512;                      // [512]

    const int tid  = threadIdx.x;
    const int w    = tid >> 5;
    const int lane = tid & 31;
    const int bid  = blockIdx.x;
    const int n0   = bid * 32;     // col' slice
    const int j0   = bid * 8;      // hidden units owned
    const int mw   = w >> 1;       // 0..3
    const int nw   = w & 1;        // 0..1

    sact[tid] = g_active[tid];
    if (tid < 32) sbias[tid] = bias[(tid & 3) * RNN + j0 + (tid >> 2)];
    if (tid < 256) { cs[tid] = 0.f; cs[tid + 256] = 0.f;
                     pooled_s[tid] = 0.f; pooled_s[tid + 256] = 0.f; }

    // ---- resident B: chunks 0..15 = Uhi, 16..31 = Ulo (32 n x 64 k each) ----
    #pragma unroll
    for (int r = 0; r < 32; r++) {
        const int o  = tid + 256 * r;    // 0..8191
        const int ch = o >> 8;           // 0..31
        const int n  = (o >> 3) & 31;
        const int cb = o & 7;
        uint32_t off = (uint32_t)(n * 128 + cb * 16);
        uint32_t sw  = off ^ ((off >> 3) & 0x70);
        const __nv_bfloat16* src =
            (ch < 16 ? g_UThi + (size_t)(n0 + n) * RNN + ch * 64
                     : g_UTlo + (size_t)(n0 + n) * RNN + (ch - 16) * 64) + cb * 8;
        cp_async16(tb + ch * 4096 + sw, src);
    }
    CP_COMMIT();
    asm volatile("cp.async.wait_group 0;" ::: "memory");
    __syncthreads();

    const int lrow = ((lane >> 3) & 1) * 8 + (lane & 7);
    const int lcolb = (lane >> 4) * 16;

    int epoch = 0;
    int rb = 0;

    for (int t = 0; t < NT; t++) {
        if (!sact[t]) continue;
        const __nv_bfloat16* Asrc = g_H2[rb];   // [64][2048]

        float c[2][2][4];   // [mt: hi/lo rows][n8 half][regs]
        #pragma unroll
        for (int i = 0; i < 2; i++)
            #pragma unroll
            for (int h = 0; h < 2; h++)
                #pragma unroll
                for (int r = 0; r < 4; r++) c[i][h][r] = 0.f;

        auto load_a = [&](int ch, int slot) {
            const uint32_t ab = ab0 + slot * A_CHUNK;
            #pragma unroll
            for (int r = 0; r < 4; r++) {
                const int o   = tid + 256 * r;   // 0..1023
                const int row = o >> 3;          // 0..127
                const int cb  = o & 7;
                uint32_t off = (uint32_t)(row * 128 + cb * 16);
                uint32_t sw  = off ^ ((off >> 3) & 0x70);
                const __nv_bfloat16* src = (row < 64)
                    ? Asrc + (size_t)row * 2048 + ch * 64 + cb * 8
                    : Asrc + (size_t)(row - 64) * 2048 + 1024 + ch * 64 + cb * 8;
                cp_async16(ab + sw, src);
            }
            CP_COMMIT();
        };

        load_a(0, 0);
        load_a(1, 1);

        for (int ch = 0; ch < 16; ch++) {
            if (ch < 15) asm volatile("cp.async.wait_group 1;" ::: "memory");
            else         asm volatile("cp.async.wait_group 0;" ::: "memory");
            __syncthreads();
            if (ch + 2 < 16) load_a(ch + 2, (ch + 2) % A_BUFS);

            const uint32_t ab = ab0 + (ch % A_BUFS) * A_CHUNK;

            #pragma unroll
            for (int kk = 0; kk < 4; kk++) {
                uint32_t boff = (uint32_t)((nw * 16 + lrow) * 128 + kk * 32 + lcolb);
                uint32_t bsw  = boff ^ ((boff >> 3) & 0x70);
                uint32_t b0, b1, b2, b3, d0, d1, d2, d3;
                ldsm_x4(b0, b1, b2, b3, tb + ch * 4096 + bsw);          // Uhi
                ldsm_x4(d0, d1, d2, d3, tb + (16 + ch) * 4096 + bsw);   // Ulo
                #pragma unroll
                for (int mt = 0; mt < 2; mt++) {
                    uint32_t aoff = (uint32_t)((mt * 64 + mw * 16 + lrow) * 128 + kk * 32 + lcolb);
                    uint32_t aaddr = ab + (aoff ^ ((aoff >> 3) & 0x70));
                    uint32_t a0, a1, a2, a3;
                    ldsm_x4(a0, a1, a2, a3, aaddr);
                    mma_bf16(c[mt][0], a0, a1, a2, a3, b0, b2);
                    mma_bf16(c[mt][1], a0, a1, a2, a3, b1, b3);
                    mma_bf16(c[mt][0], a0, a1, a2, a3, d0, d2);
                    mma_bf16(c[mt][1], a0, a1, a2, a3, d1, d3);
                }
            }
        }
        __syncthreads();   // all warps done with last A buffer & ready for zbuf

        // epilogue: fold hi rows (mt0) + lo rows (mt1) -> exact z, in smem
        #pragma unroll
        for (int h = 0; h < 2; h++) {
            const int row = mw * 16 + (lane >> 2);
            const int col = nw * 16 + h * 8 + (lane & 3) * 2;
            zbuf[row * 33 + col]           = c[0][h][0] + c[1][h][0];
            zbuf[row * 33 + col + 1]       = c[0][h][1] + c[1][h][1];
            zbuf[(row + 8) * 33 + col]     = c[0][h][2] + c[1][h][2];
            zbuf[(row + 8) * 33 + col + 1] = c[0][h][3] + c[1][h][3];
        }
        __syncthreads();

        // block-local cell update: 512 cells (8 units x 64 batches)
        __nv_bfloat16* hw = g_H2[rb ^ 1];
        const __nv_bfloat16* hr = g_H2[rb];
        #pragma unroll
        for (int r = 0; r < 2; r++) {
            const int cell = r * 256 + tid;      // 0..511
            const int b  = cell >> 3;            // 0..63
            const int jl = cell & 7;             // 0..7
            const int j  = j0 + jl;

            float4 xw4 = *reinterpret_cast<const float4*>(
                g_XW + ((size_t)t * NB + b) * Z4 + (size_t)(n0 + jl * 4));
            const float zi = xw4.x + zbuf[b * 33 + jl * 4 + 0] + sbias[jl * 4 + 0];
            const float zf = xw4.y + zbuf[b * 33 + jl * 4 + 1] + sbias[jl * 4 + 1];
            const float zg = xw4.z + zbuf[b * 33 + jl * 4 + 2] + sbias[jl * 4 + 2];
            const float zo = xw4.w + zbuf[b * 33 + jl * 4 + 3] + sbias[jl * 4 + 3];

            const float si = 1.f / (1.f + expf(-zi));
            const float sf = 1.f / (1.f + expf(-zf));
            const float so = 1.f / (1.f + expf(-zo));
            const float cn = sf * cs[cell] + si * tanhf(zg);
            const float hn = so * tanhf(cn);
            const int xv = x[b * NT + t];
            if (xv != 0) {
                cs[cell] = cn;
                __nv_bfloat16 hi = __float2bfloat16(hn);
                hw[b * 2048 + j] = hi;
                hw[b * 2048 + 1024 + j] = __float2bfloat16(hn - __bfloat162float(hi));
            } else {
                hw[b * 2048 + j] = hr[b * 2048 + j];
                hw[b * 2048 + 1024 + j] = hr[b * 2048 + 1024 + j];
            }
            if (xv == 2) pooled_s[cell] += hn;
        }

        // ---- single grid barrier per step ----
        epoch++;
        __threadfence();
        __syncthreads();
        if (tid == 0) {
            unsigned old = atomicAdd(&g_arrive, 1u);
            if (old == 127u) {
                g_arrive = 0;
                asm volatile("st.release.gpu.global.s32 [%0], %1;"
                             :: "l"(&g_release), "r"(epoch) : "memory");
            } else {
                int v;
                do {
                    asm volatile("ld.acquire.gpu.global.s32 %0, [%1];"
                                 : "=r"(v) : "l"(&g_release) : "memory");
                } while (v < epoch);
            }
        }
        __syncthreads();
        __threadfence();

        rb ^= 1;
    }

    // write pooled out
    #pragma unroll
    for (int r = 0; r < 2; r++) {
        const int cell = r * 256 + tid;
        const int b  = cell >> 3;
        const int jl = cell & 7;
        g_pooled[b * RNN + j0 + jl] = pooled_s[cell];
    }
}

// ---------------- head -----------------------------------------------------
__global__ __launch_bounds__(128) void head_kernel(const float* __restrict__ W1,
                                                   const float* __restrict__ b1,
                                                   const float* __restrict__ W2,
                                                   const float* __restrict__ b2,
                                                   const float* __restrict__ Wc,
                                                   const float* __restrict__ bc,
                                                   float* __restrict__ out) {
    const int b = blockIdx.x;
    const int tid = threadIdx.x;
    __shared__ float sp[RNN];
    __shared__ float h1s[HIDN];
    __shared__ float h2s[HIDN];
    __shared__ float lg[NLAB];

    for (int k = tid; k < RNN; k += 128) sp[k] = g_pooled[(size_t)b * RNN + k];
    __syncthreads();

    float a = b1[tid];
    for (int k = 0; k < RNN; k++) a += sp[k] * W1[(size_t)k * HIDN + tid];
    h1s[tid] = fmaxf(a, 0.f);
    __syncthreads();

    float a2 = b2[tid];
    for (int k = 0; k < HIDN; k++) a2 += h1s[k] * W2[(size_t)k * HIDN + tid];
    h2s[tid] = fmaxf(a2, 0.f);
    __syncthreads();

    if (tid < NLAB) {
        float l = bc[tid];
        for (int k = 0; k < HIDN; k++) l += h2s[k] * Wc[(size_t)k * NLAB + tid];
        lg[tid] = l;
    }
    __syncthreads();
    if (tid == 0) {
        const float mx = fmaxf(fmaxf(lg[0], lg[1]), fmaxf(lg[2], lg[3]));
        const float e0 = expf(lg[0] - mx), e1 = expf(lg[1] - mx);
        const float e2 = expf(lg[2] - mx), e3 = expf(lg[3] - mx);
        const float sden = e0 + e1 + e2 + e3;
        out[b * 4 + 0] = e0 / sden; out[b * 4 + 1] = e1 / sden;
        out[b * 4 + 2] = e2 / sden; out[b * 4 + 3] = e3 / sden;
    }
}

// ---------------- launcher -------------------------------------------------
extern "C" void kernel_launch(void* const* d_in, const int* in_sizes, int n_in,
                              void* d_out, int out_size) {
    const int*   x    = (const int*)d_in[0];
    const float* emb  = (const float*)d_in[1];
    const float* W    = (const float*)d_in[2];
    const float* U    = (const float*)d_in[3];
    const float* bias = (const float*)d_in[4];
    const float* W1   = (const float*)d_in[5];
    const float* b1   = (const float*)d_in[6];
    const float* W2   = (const float*)d_in[7];
    const float* b2   = (const float*)d_in[8];
    const float* Wc   = (const float*)d_in[9];
    const float* bc   = (const float*)d_in[10];
    float* out = (float*)d_out;

    cudaFuncSetAttribute(xw_mma_kernel, cudaFuncAttributeMaxDynamicSharedMemorySize, GEMM_SMEM);
    cudaFuncSetAttribute(rnn_persist, cudaFuncAttributeMaxDynamicSharedMemorySize, RNN_SMEM);

    prep_kernel<<<1, 256>>>(x);
    zero_kernel<<<512, 256>>>();
    esplit_kernel<<<(VOCAB * EMBD) / 256, 256>>>(emb);
    upack_kernel<<<dim3(RNN / 64, Z4 / 64), 256>>>(U);
    wpack_kernel<<<dim3(EMBD / 64, Z4 / 64), 256>>>(W);
    xw_mma_kernel<<<dim3(32, NT), 256, GEMM_SMEM>>>(x);
    rnn_persist<<<128, 256, RNN_SMEM>>>(x, bias);
    head_kernel<<<NB, 128>>>(W1, b1, W2, b2, Wc, bc, out);
}

// round 11
// speedup vs baseline: 1.5611x; 1.1517x over previous
#include <cuda_runtime.h>
#include <cuda_bf16.h>
#include <math.h>
#include <stdint.h>

#define NB   64
#define NT   256
#define EMBD 512
#define VOCAB 32000
#define RNN  1024
#define Z4   4096
#define HIDN 128
#define NLAB 4

// Column permutation: original n = gate*1024 + j  ->  col' = j*4 + gate.

// ---------------- static device scratch ----------------------------------
__device__ float g_XW[(size_t)NT * NB * Z4];            // emb[x] @ W  (col' layout)
__device__ __nv_bfloat16 g_UThi[(size_t)Z4 * RNN];      // U^T hi, [col'][k]
__device__ __nv_bfloat16 g_UTlo[(size_t)Z4 * RNN];
__device__ __nv_bfloat16 g_WThi[(size_t)Z4 * EMBD];
__device__ __nv_bfloat16 g_WTlo[(size_t)Z4 * EMBD];
__device__ __nv_bfloat16 g_Ehi[(size_t)VOCAB * EMBD];
__device__ __nv_bfloat16 g_Elo[(size_t)VOCAB * EMBD];
__device__ __nv_bfloat16 g_H2[2][64 * 2048];            // ping-pong: row b = [hi(1024) | lo(1024)]
__device__ float g_pooled[NB * RNN];
__device__ int   g_active[NT];
__device__ unsigned g_arrive;
__device__ int   g_release;

// ---------------- helpers --------------------------------------------------
__device__ __forceinline__ uint32_t smem_u32(const void* p) {
    return (uint32_t)__cvta_generic_to_shared(p);
}
__device__ __forceinline__ void cp_async16(uint32_t smem_dst, const void* gsrc) {
    asm volatile("cp.async.cg.shared.global [%0], [%1], 16;" :: "r"(smem_dst), "l"(gsrc));
}
#define CP_COMMIT() asm volatile("cp.async.commit_group;" ::: "memory")

__device__ __forceinline__ void ldsm_x4(uint32_t& r0, uint32_t& r1,
                                        uint32_t& r2, uint32_t& r3, uint32_t addr) {
    asm volatile("ldmatrix.sync.aligned.m8n8.x4.shared.b16 {%0,%1,%2,%3}, [%4];"
                 : "=r"(r0), "=r"(r1), "=r"(r2), "=r"(r3) : "r"(addr));
}
__device__ __forceinline__ void mma_bf16(float* c, uint32_t a0, uint32_t a1,
                                         uint32_t a2, uint32_t a3,
                                         uint32_t b0, uint32_t b1) {
    asm volatile("mma.sync.aligned.m16n8k16.row.col.f32.bf16.bf16.f32 "
                 "{%0,%1,%2,%3}, {%4,%5,%6,%7}, {%8,%9}, {%0,%1,%2,%3};"
                 : "+f"(c[0]), "+f"(c[1]), "+f"(c[2]), "+f"(c[3])
                 : "r"(a0), "r"(a1), "r"(a2), "r"(a3), "r"(b0), "r"(b1));
}

// ---------------- prep -----------------------------------------------------
__global__ void prep_kernel(const int* __restrict__ x) {
    int t = threadIdx.x;
    if (t < NT) {
        int act = 0;
        for (int b = 0; b < NB; b++) act |= (x[b * NT + t] != 0);
        g_active[t] = act;
    }
    if (t == 0) { g_arrive = 0; g_release = 0; }
}

__global__ void zero_kernel() {
    int i = blockIdx.x * blockDim.x + threadIdx.x;   // 512*256 = 131072
    ((uint32_t*)g_H2)[i] = 0u;                       // both ping-pong buffers
}

// ---------------- emb split ------------------------------------------------
__global__ __launch_bounds__(256) void esplit_kernel(const float* __restrict__ emb) {
    size_t i = (size_t)blockIdx.x * 256 + threadIdx.x;
    float v = emb[i];
    __nv_bfloat16 hi = __float2bfloat16(v);
    g_Ehi[i] = hi;
    g_Elo[i] = __float2bfloat16(v - __bfloat162float(hi));
}

// ---------------- transpose+split+permute: U and W -------------------------
__device__ __forceinline__ int permute_col(int n) {
    return (n & 1023) * 4 + (n >> 10);
}

__global__ __launch_bounds__(256) void upack_kernel(const float* __restrict__ U) {
    __shared__ float tile[64][65];
    const int k0 = blockIdx.x * 64;
    const int n0 = blockIdx.y * 64;
    const int tid = threadIdx.x;
    #pragma unroll
    for (int it = 0; it < 16; it++) {
        int r = it * 4 + (tid >> 6);
        int c = tid & 63;
        tile[r][c] = U[(size_t)(k0 + r) * Z4 + n0 + c];
    }
    __syncthreads();
    #pragma unroll
    for (int it = 0; it < 16; it++) {
        int n = it * 4 + (tid >> 6);
        int k = tid & 63;
        float v = tile[k][n];
        __nv_bfloat16 hi = __float2bfloat16(v);
        const int np = permute_col(n0 + n);
        g_UThi[(size_t)np * RNN + k0 + k] = hi;
        g_UTlo[(size_t)np * RNN + k0 + k] =
            __float2bfloat16(v - __bfloat162float(hi));
    }
}

__global__ __launch_bounds__(256) void wpack_kernel(const float* __restrict__ W) {
    __shared__ float tile[64][65];
    const int k0 = blockIdx.x * 64;
    const int n0 = blockIdx.y * 64;
    const int tid = threadIdx.x;
    #pragma unroll
    for (int it = 0; it < 16; it++) {
        int r = it * 4 + (tid >> 6);
        int c = tid & 63;
        tile[r][c] = W[(size_t)(k0 + r) * Z4 + n0 + c];
    }
    __syncthreads();
    #pragma unroll
    for (int it = 0; it < 16; it++) {
        int n = it * 4 + (tid >> 6);
        int k = tid & 63;
        float v = tile[k][n];
        __nv_bfloat16 hi = __float2bfloat16(v);
        const int np = permute_col(n0 + n);
        g_WThi[(size_t)np * EMBD + k0 + k] = hi;
        g_WTlo[(size_t)np * EMBD + k0 + k] =
            __float2bfloat16(v - __bfloat162float(hi));
    }
}

// ---------------- HMMA input projection (3-term: skip e_lo@W_lo) -----------
#define BUF_BYTES 32768
#define GEMM_SMEM (1024 + 2 * BUF_BYTES)
#define XCHUNKS 16

__global__ __launch_bounds__(256) void xw_mma_kernel(const int* __restrict__ x) {
    const int t = blockIdx.y;
    if (!g_active[t]) return;

    extern __shared__ char dyn[];
    __shared__ int idxs[64];
    const uint32_t tb = (smem_u32(dyn) + 1023u) & ~1023u;

    const int tid  = threadIdx.x;
    const int w    = tid >> 5;
    const int lane = tid & 31;
    const int n0   = blockIdx.x * 128;
    const int mw   = w >> 1;
    const int nw   = w & 1;

    if (tid < 64) idxs[tid] = x[tid * NT + t];
    __syncthreads();

    float c[2][4][2][4];
    #pragma unroll
    for (int i = 0; i < 2; i++)
        #pragma unroll
        for (int j = 0; j < 4; j++)
            #pragma unroll
            for (int h = 0; h < 2; h++)
                #pragma unroll
                for (int r = 0; r < 4; r++) c[i][j][h][r] = 0.f;

    auto load_chunk = [&](int ch, int slot) {
        const uint32_t ab = tb + slot * BUF_BYTES;
        const uint32_t bb = ab + 16384;
        const int pass = ch >> 3;
        const int kg = (ch & 7) * 64;
        const __nv_bfloat16* Bsrc =
            (pass ? g_WTlo : g_WThi) + (size_t)n0 * EMBD + kg;
        #pragma unroll
        for (int r = 0; r < 4; r++) {
            const int o   = tid + 256 * r;
            const int row = o >> 3;
            const int cb  = o & 7;
            uint32_t off = (uint32_t)(row * 128 + cb * 16);
            uint32_t sw  = off ^ ((off >> 3) & 0x70);
            const __nv_bfloat16* asrc =
                (row < 64) ? (g_Ehi + (size_t)idxs[row] * EMBD + kg + cb * 8)
                           : (g_Elo + (size_t)idxs[row - 64] * EMBD + kg + cb * 8);
            cp_async16(ab + sw, asrc);
            cp_async16(bb + sw, Bsrc + (size_t)row * EMBD + cb * 8);
        }
        CP_COMMIT();
    };

    load_chunk(0, 0);

    const int lrow = ((lane >> 3) & 1) * 8 + (lane & 7);
    const int lcolb = (lane >> 4) * 16;

    for (int ch = 0; ch < XCHUNKS; ch++) {
        if (ch + 1 < XCHUNKS) load_chunk(ch + 1, (ch + 1) & 1);
        if (ch + 1 < XCHUNKS) asm volatile("cp.async.wait_group 1;" ::: "memory");
        else                  asm volatile("cp.async.wait_group 0;" ::: "memory");
        __syncthreads();

        const uint32_t ab = tb + (ch & 1) * BUF_BYTES;
        const uint32_t bb = ab + 16384;
        const bool pass1 = (ch >= 8);

        #pragma unroll
        for (int kk = 0; kk < 4; kk++) {
            uint32_t bf[4][4];
            #pragma unroll
            for (int nt = 0; nt < 4; nt++) {
                uint32_t boff = (uint32_t)((nw * 64 + nt * 16 + lrow) * 128 + kk * 32 + lcolb);
                uint32_t baddr = bb + (boff ^ ((boff >> 3) & 0x70));
                ldsm_x4(bf[nt][0], bf[nt][1], bf[nt][2], bf[nt][3], baddr);
            }
            #pragma unroll
            for (int mt = 0; mt < 2; mt++) {
                if (mt == 1 && pass1) continue;   // drop e_lo @ W_lo (~2^-16)
                const int mbase = mt * 64 + mw * 16;
                uint32_t aoff = (uint32_t)((mbase + lrow) * 128 + kk * 32 + lcolb);
                uint32_t aaddr = ab + (aoff ^ ((aoff >> 3) & 0x70));
                uint32_t a0, a1, a2, a3;
                ldsm_x4(a0, a1, a2, a3, aaddr);
                #pragma unroll
                for (int nt = 0; nt < 4; nt++) {
                    mma_bf16(c[mt][nt][0], a0, a1, a2, a3, bf[nt][0], bf[nt][2]);
                    mma_bf16(c[mt][nt][1], a0, a1, a2, a3, bf[nt][1], bf[nt][3]);
                }
            }
        }
        __syncthreads();
    }

    float* C = g_XW + (size_t)t * NB * Z4;
    #pragma unroll
    for (int nt = 0; nt < 4; nt++) {
        #pragma unroll
        for (int h = 0; h < 2; h++) {
            const int row = mw * 16 + (lane >> 2);
            const int col = n0 + nw * 64 + nt * 16 + h * 8 + (lane & 3) * 2;
            float2 v01 = make_float2(c[0][nt][h][0] + c[1][nt][h][0],
                                     c[0][nt][h][1] + c[1][nt][h][1]);
            float2 v23 = make_float2(c[0][nt][h][2] + c[1][nt][h][2],
                                     c[0][nt][h][3] + c[1][nt][h][3]);
            *reinterpret_cast<float2*>(C + (size_t)row * Z4 + col) = v01;
            *reinterpret_cast<float2*>(C + (size_t)(row + 8) * Z4 + col) = v23;
        }
    }
}

// ---------------- persistent recurrence: 3-term, block-local z --------------
// 128 blocks x 256 thr, 1 CTA/SM. Block owns 32 col' (= 8 hidden units).
// A = [h_hi(64); h_lo(64)] (M=128), B resident (Uhi|Ulo K-stacked).
// mt=0 (hi rows): x Uhi and x Ulo.  mt=1 (lo rows): x Uhi only (drop lo@lo).
#define A_BUFS   3
#define A_CHUNK  16384
#define B_BYTES  131072
#define ZB_OFF   (B_BYTES + A_BUFS * A_CHUNK)
#define CS_OFF   (ZB_OFF + 64 * 33 * 4)
#define RNN_SMEM (1024 + CS_OFF + 4096)

__global__ __launch_bounds__(256, 1) void rnn_persist(const int* __restrict__ x,
                                                      const float* __restrict__ bias) {
    extern __shared__ char dyn[];
    __shared__ int sact[NT];
    __shared__ float sbias[32];
    const uint32_t dynb = smem_u32(dyn);
    const uint32_t tb   = (dynb + 1023u) & ~1023u;   // B: 32 chunks x 4KB
    const uint32_t ab0  = tb + B_BYTES;              // A: 3 x 16KB
    char* dynal = dyn + (tb - dynb);
    float* zbuf     = (float*)(dynal + ZB_OFF);      // [64][33]
    float* cs       = (float*)(dynal + CS_OFF);      // [512]
    float* pooled_s = cs + 512;                      // [512]

    const int tid  = threadIdx.x;
    const int w    = tid >> 5;
    const int lane = tid & 31;
    const int bid  = blockIdx.x;
    const int n0   = bid * 32;     // col' slice
    const int j0   = bid * 8;      // hidden units owned
    const int mw   = w >> 1;       // 0..3
    const int nw   = w & 1;        // 0..1

    sact[tid] = g_active[tid];
    if (tid < 32) sbias[tid] = bias[(tid & 3) * RNN + j0 + (tid >> 2)];
    if (tid < 256) { cs[tid] = 0.f; cs[tid + 256] = 0.f;
                     pooled_s[tid] = 0.f; pooled_s[tid + 256] = 0.f; }

    // ---- resident B: chunks 0..15 = Uhi, 16..31 = Ulo (32 n x 64 k each) ----
    #pragma unroll
    for (int r = 0; r < 32; r++) {
        const int o  = tid + 256 * r;    // 0..8191
        const int ch = o >> 8;           // 0..31
        const int n  = (o >> 3) & 31;
        const int cb = o & 7;
        uint32_t off = (uint32_t)(n * 128 + cb * 16);
        uint32_t sw  = off ^ ((off >> 3) & 0x70);
        const __nv_bfloat16* src =
            (ch < 16 ? g_UThi + (size_t)(n0 + n) * RNN + ch * 64
                     : g_UTlo + (size_t)(n0 + n) * RNN + (ch - 16) * 64) + cb * 8;
        cp_async16(tb + ch * 4096 + sw, src);
    }
    CP_COMMIT();
    asm volatile("cp.async.wait_group 0;" ::: "memory");
    __syncthreads();

    const int lrow = ((lane >> 3) & 1) * 8 + (lane & 7);
    const int lcolb = (lane >> 4) * 16;

    int epoch = 0;
    int rb = 0;

    for (int t = 0; t < NT; t++) {
        if (!sact[t]) continue;
        const __nv_bfloat16* Asrc = g_H2[rb];   // [64][2048]

        float c[2][2][4];   // [mt: hi/lo rows][n8 half][regs]
        #pragma unroll
        for (int i = 0; i < 2; i++)
            #pragma unroll
            for (int h = 0; h < 2; h++)
                #pragma unroll
                for (int r = 0; r < 4; r++) c[i][h][r] = 0.f;

        auto load_a = [&](int ch, int slot) {
            const uint32_t ab = ab0 + slot * A_CHUNK;
            #pragma unroll
            for (int r = 0; r < 4; r++) {
                const int o   = tid + 256 * r;   // 0..1023
                const int row = o >> 3;          // 0..127
                const int cb  = o & 7;
                uint32_t off = (uint32_t)(row * 128 + cb * 16);
                uint32_t sw  = off ^ ((off >> 3) & 0x70);
                const __nv_bfloat16* src = (row < 64)
                    ? Asrc + (size_t)row * 2048 + ch * 64 + cb * 8
                    : Asrc + (size_t)(row - 64) * 2048 + 1024 + ch * 64 + cb * 8;
                cp_async16(ab + sw, src);
            }
            CP_COMMIT();
        };

        load_a(0, 0);
        load_a(1, 1);

        for (int ch = 0; ch < 16; ch++) {
            if (ch < 15) asm volatile("cp.async.wait_group 1;" ::: "memory");
            else         asm volatile("cp.async.wait_group 0;" ::: "memory");
            __syncthreads();
            if (ch + 2 < 16) load_a(ch + 2, (ch + 2) % A_BUFS);

            const uint32_t ab = ab0 + (ch % A_BUFS) * A_CHUNK;

            #pragma unroll
            for (int kk = 0; kk < 4; kk++) {
                uint32_t boff = (uint32_t)((nw * 16 + lrow) * 128 + kk * 32 + lcolb);
                uint32_t bsw  = boff ^ ((boff >> 3) & 0x70);
                uint32_t b0, b1, b2, b3, d0, d1, d2, d3;
                ldsm_x4(b0, b1, b2, b3, tb + ch * 4096 + bsw);          // Uhi
                ldsm_x4(d0, d1, d2, d3, tb + (16 + ch) * 4096 + bsw);   // Ulo

                // mt=0: h_hi rows x (Uhi + Ulo)
                {
                    uint32_t aoff = (uint32_t)((mw * 16 + lrow) * 128 + kk * 32 + lcolb);
                    uint32_t aaddr = ab + (aoff ^ ((aoff >> 3) & 0x70));
                    uint32_t a0, a1, a2, a3;
                    ldsm_x4(a0, a1, a2, a3, aaddr);
                    mma_bf16(c[0][0], a0, a1, a2, a3, b0, b2);
                    mma_bf16(c[0][1], a0, a1, a2, a3, b1, b3);
                    mma_bf16(c[0][0], a0, a1, a2, a3, d0, d2);
                    mma_bf16(c[0][1], a0, a1, a2, a3, d1, d3);
                }
                // mt=1: h_lo rows x Uhi only (drop lo@lo, ~2^-16)
                {
                    uint32_t aoff = (uint32_t)((64 + mw * 16 + lrow) * 128 + kk * 32 + lcolb);
                    uint32_t aaddr = ab + (aoff ^ ((aoff >> 3) & 0x70));
                    uint32_t a0, a1, a2, a3;
                    ldsm_x4(a0, a1, a2, a3, aaddr);
                    mma_bf16(c[1][0], a0, a1, a2, a3, b0, b2);
                    mma_bf16(c[1][1], a0, a1, a2, a3, b1, b3);
                }
            }
        }
        __syncthreads();

        // epilogue: fold hi rows + lo rows -> z, in smem
        #pragma unroll
        for (int h = 0; h < 2; h++) {
            const int row = mw * 16 + (lane >> 2);
            const int col = nw * 16 + h * 8 + (lane & 3) * 2;
            zbuf[row * 33 + col]           = c[0][h][0] + c[1][h][0];
            zbuf[row * 33 + col + 1]       = c[0][h][1] + c[1][h][1];
            zbuf[(row + 8) * 33 + col]     = c[0][h][2] + c[1][h][2];
            zbuf[(row + 8) * 33 + col + 1] = c[0][h][3] + c[1][h][3];
        }
        __syncthreads();

        // block-local cell update: 512 cells (8 units x 64 batches)
        __nv_bfloat16* hw = g_H2[rb ^ 1];
        const __nv_bfloat16* hr = g_H2[rb];
        #pragma unroll
        for (int r = 0; r < 2; r++) {
            const int cell = r * 256 + tid;      // 0..511
            const int b  = cell >> 3;            // 0..63
            const int jl = cell & 7;             // 0..7
            const int j  = j0 + jl;

            float4 xw4 = *reinterpret_cast<const float4*>(
                g_XW + ((size_t)t * NB + b) * Z4 + (size_t)(n0 + jl * 4));
            const float zi = xw4.x + zbuf[b * 33 + jl * 4 + 0] + sbias[jl * 4 + 0];
            const float zf = xw4.y + zbuf[b * 33 + jl * 4 + 1] + sbias[jl * 4 + 1];
            const float zg = xw4.z + zbuf[b * 33 + jl * 4 + 2] + sbias[jl * 4 + 2];
            const float zo = xw4.w + zbuf[b * 33 + jl * 4 + 3] + sbias[jl * 4 + 3];

            const float si = 1.f / (1.f + expf(-zi));
            const float sf = 1.f / (1.f + expf(-zf));
            const float so = 1.f / (1.f + expf(-zo));
            const float cn = sf * cs[cell] + si * tanhf(zg);
            const float hn = so * tanhf(cn);
            const int xv = x[b * NT + t];
            if (xv != 0) {
                cs[cell] = cn;
                __nv_bfloat16 hi = __float2bfloat16(hn);
                hw[b * 2048 + j] = hi;
                hw[b * 2048 + 1024 + j] = __float2bfloat16(hn - __bfloat162float(hi));
            } else {
                hw[b * 2048 + j] = hr[b * 2048 + j];
                hw[b * 2048 + 1024 + j] = hr[b * 2048 + 1024 + j];
            }
            if (xv == 2) pooled_s[cell] += hn;
        }

        // ---- single grid barrier per step ----
        epoch++;
        __threadfence();
        __syncthreads();
        if (tid == 0) {
            unsigned old = atomicAdd(&g_arrive, 1u);
            if (old == 127u) {
                g_arrive = 0;
                asm volatile("st.release.gpu.global.s32 [%0], %1;"
                             :: "l"(&g_release), "r"(epoch) : "memory");
            } else {
                int v;
                do {
                    asm volatile("ld.acquire.gpu.global.s32 %0, [%1];"
                                 : "=r"(v) : "l"(&g_release) : "memory");
                } while (v < epoch);
            }
        }
        __syncthreads();
        __threadfence();

        rb ^= 1;
    }

    // write pooled out
    #pragma unroll
    for (int r = 0; r < 2; r++) {
        const int cell = r * 256 + tid;
        const int b  = cell >> 3;
        const int jl = cell & 7;
        g_pooled[b * RNN + j0 + jl] = pooled_s[cell];
    }
}

// ---------------- head -----------------------------------------------------
__global__ __launch_bounds__(128) void head_kernel(const float* __restrict__ W1,
                                                   const float* __restrict__ b1,
                                                   const float* __restrict__ W2,
                                                   const float* __restrict__ b2,
                                                   const float* __restrict__ Wc,
                                                   const float* __restrict__ bc,
                                                   float* __restrict__ out) {
    const int b = blockIdx.x;
    const int tid = threadIdx.x;
    __shared__ float sp[RNN];
    __shared__ float h1s[HIDN];
    __shared__ float h2s[HIDN];
    __shared__ float lg[NLAB];

    for (int k = tid; k < RNN; k += 128) sp[k] = g_pooled[(size_t)b * RNN + k];
    __syncthreads();

    float a = b1[tid];
    for (int k = 0; k < RNN; k++) a += sp[k] * W1[(size_t)k * HIDN + tid];
    h1s[tid] = fmaxf(a, 0.f);
    __syncthreads();

    float a2 = b2[tid];
    for (int k = 0; k < HIDN; k++) a2 += h1s[k] * W2[(size_t)k * HIDN + tid];
    h2s[tid] = fmaxf(a2, 0.f);
    __syncthreads();

    if (tid < NLAB) {
        float l = bc[tid];
        for (int k = 0; k < HIDN; k++) l += h2s[k] * Wc[(size_t)k * NLAB + tid];
        lg[tid] = l;
    }
    __syncthreads();
    if (tid == 0) {
        const float mx = fmaxf(fmaxf(lg[0], lg[1]), fmaxf(lg[2], lg[3]));
        const float e0 = expf(lg[0] - mx), e1 = expf(lg[1] - mx);
        const float e2 = expf(lg[2] - mx), e3 = expf(lg[3] - mx);
        const float sden = e0 + e1 + e2 + e3;
        out[b * 4 + 0] = e0 / sden; out[b * 4 + 1] = e1 / sden;
        out[b * 4 + 2] = e2 / sden; out[b * 4 + 3] = e3 / sden;
    }
}

// ---------------- launcher -------------------------------------------------
extern "C" void kernel_launch(void* const* d_in, const int* in_sizes, int n_in,
                              void* d_out, int out_size) {
    const int*   x    = (const int*)d_in[0];
    const float* emb  = (const float*)d_in[1];
    const float* W    = (const float*)d_in[2];
    const float* U    = (const float*)d_in[3];
    const float* bias = (const float*)d_in[4];
    const float* W1   = (const float*)d_in[5];
    const float* b1   = (const float*)d_in[6];
    const float* W2   = (const float*)d_in[7];
    const float* b2   = (const float*)d_in[8];
    const float* Wc   = (const float*)d_in[9];
    const float* bc   = (const float*)d_in[10];
    float* out = (float*)d_out;

    cudaFuncSetAttribute(xw_mma_kernel, cudaFuncAttributeMaxDynamicSharedMemorySize, GEMM_SMEM);
    cudaFuncSetAttribute(rnn_persist, cudaFuncAttributeMaxDynamicSharedMemorySize, RNN_SMEM);

    prep_kernel<<<1, 256>>>(x);
    zero_kernel<<<512, 256>>>();
    esplit_kernel<<<(VOCAB * EMBD) / 256, 256>>>(emb);
    upack_kernel<<<dim3(RNN / 64, Z4 / 64), 256>>>(U);
    wpack_kernel<<<dim3(EMBD / 64, Z4 / 64), 256>>>(W);
    xw_mma_kernel<<<dim3(32, NT), 256, GEMM_SMEM>>>(x);
    rnn_persist<<<128, 256, RNN_SMEM>>>(x, bias);
    head_kernel<<<NB, 128>>>(W1, b1, W2, b2, Wc, bc, out);
}

// round 12
// speedup vs baseline: 1.7729x; 1.1357x over previous
#include <cuda_runtime.h>
#include <cuda_fp16.h>
#include <math.h>
#include <stdint.h>

#define NB   64
#define NT   256
#define EMBD 512
#define VOCAB 32000
#define RNN  1024
#define Z4   4096
#define HIDN 128
#define NLAB 4

// Column permutation: original n = gate*1024 + j  ->  col' = j*4 + gate.
// fp16 scheme: h, e single fp16 (random per-step quantization, damps);
// U, W split hi+lo fp16 (systematic weight error ~2^-22, negligible).

// ---------------- static device scratch ----------------------------------
__device__ float g_XW[(size_t)NT * NB * Z4];            // emb[x] @ W  (col' layout)
__device__ __half g_UThi[(size_t)Z4 * RNN];             // U^T hi, [col'][k]
__device__ __half g_UTlo[(size_t)Z4 * RNN];
__device__ __half g_WThi[(size_t)Z4 * EMBD];
__device__ __half g_WTlo[(size_t)Z4 * EMBD];
__device__ __half g_Ef16[(size_t)VOCAB * EMBD];
__device__ __half g_H2[2][64 * RNN];                    // ping-pong h (fp16)
__device__ float g_pooled[NB * RNN];
__device__ int   g_active[NT];
__device__ unsigned g_arrive;
__device__ int   g_release;

// ---------------- helpers --------------------------------------------------
__device__ __forceinline__ uint32_t smem_u32(const void* p) {
    return (uint32_t)__cvta_generic_to_shared(p);
}
__device__ __forceinline__ void cp_async16(uint32_t smem_dst, const void* gsrc) {
    asm volatile("cp.async.cg.shared.global [%0], [%1], 16;" :: "r"(smem_dst), "l"(gsrc));
}
#define CP_COMMIT() asm volatile("cp.async.commit_group;" ::: "memory")

__device__ __forceinline__ void ldsm_x4(uint32_t& r0, uint32_t& r1,
                                        uint32_t& r2, uint32_t& r3, uint32_t addr) {
    asm volatile("ldmatrix.sync.aligned.m8n8.x4.shared.b16 {%0,%1,%2,%3}, [%4];"
                 : "=r"(r0), "=r"(r1), "=r"(r2), "=r"(r3) : "r"(addr));
}
__device__ __forceinline__ void mma_f16(float* c, uint32_t a0, uint32_t a1,
                                        uint32_t a2, uint32_t a3,
                                        uint32_t b0, uint32_t b1) {
    asm volatile("mma.sync.aligned.m16n8k16.row.col.f32.f16.f16.f32 "
                 "{%0,%1,%2,%3}, {%4,%5,%6,%7}, {%8,%9}, {%0,%1,%2,%3};"
                 : "+f"(c[0]), "+f"(c[1]), "+f"(c[2]), "+f"(c[3])
                 : "r"(a0), "r"(a1), "r"(a2), "r"(a3), "r"(b0), "r"(b1));
}

// ---------------- prep -----------------------------------------------------
__global__ void prep_kernel(const int* __restrict__ x) {
    int t = threadIdx.x;
    if (t < NT) {
        int act = 0;
        for (int b = 0; b < NB; b++) act |= (x[b * NT + t] != 0);
        g_active[t] = act;
    }
    if (t == 0) { g_arrive = 0; g_release = 0; }
}

__global__ void zero_kernel() {
    int i = blockIdx.x * blockDim.x + threadIdx.x;   // 256*256 = 65536
    ((uint32_t*)g_H2)[i] = 0u;                       // 2*64*1024 halfs = 65536 u32
}

// ---------------- emb -> fp16 ------------------------------------------------
__global__ __launch_bounds__(256) void esplit_kernel(const float* __restrict__ emb) {
    size_t i = (size_t)blockIdx.x * 256 + threadIdx.x;
    g_Ef16[i] = __float2half_rn(emb[i]);
}

// ---------------- transpose+split+permute: U and W -------------------------
__device__ __forceinline__ int permute_col(int n) {
    return (n & 1023) * 4 + (n >> 10);
}

__global__ __launch_bounds__(256) void upack_kernel(const float* __restrict__ U) {
    __shared__ float tile[64][65];
    const int k0 = blockIdx.x * 64;
    const int n0 = blockIdx.y * 64;
    const int tid = threadIdx.x;
    #pragma unroll
    for (int it = 0; it < 16; it++) {
        int r = it * 4 + (tid >> 6);
        int c = tid & 63;
        tile[r][c] = U[(size_t)(k0 + r) * Z4 + n0 + c];
    }
    __syncthreads();
    #pragma unroll
    for (int it = 0; it < 16; it++) {
        int n = it * 4 + (tid >> 6);
        int k = tid & 63;
        float v = tile[k][n];
        __half hi = __float2half_rn(v);
        const int np = permute_col(n0 + n);
        g_UThi[(size_t)np * RNN + k0 + k] = hi;
        g_UTlo[(size_t)np * RNN + k0 + k] = __float2half_rn(v - __half2float(hi));
    }
}

__global__ __launch_bounds__(256) void wpack_kernel(const float* __restrict__ W) {
    __shared__ float tile[64][65];
    const int k0 = blockIdx.x * 64;
    const int n0 = blockIdx.y * 64;
    const int tid = threadIdx.x;
    #pragma unroll
    for (int it = 0; it < 16; it++) {
        int r = it * 4 + (tid >> 6);
        int c = tid & 63;
        tile[r][c] = W[(size_t)(k0 + r) * Z4 + n0 + c];
    }
    __syncthreads();
    #pragma unroll
    for (int it = 0; it < 16; it++) {
        int n = it * 4 + (tid >> 6);
        int k = tid & 63;
        float v = tile[k][n];
        __half hi = __float2half_rn(v);
        const int np = permute_col(n0 + n);
        g_WThi[(size_t)np * EMBD + k0 + k] = hi;
        g_WTlo[(size_t)np * EMBD + k0 + k] = __float2half_rn(v - __half2float(hi));
    }
}

// ---------------- fp16 input projection: XW[t] = e @ (Whi + Wlo) -----------
// grid (32 n-tiles, NT) x 256. M=64 (e rows, fp16, RESIDENT in smem),
// N=128, B streamed: 16 chunks (pass0 Whi ch0-7, pass1 Wlo ch0-7).
#define XW_A_BYTES 65536
#define XW_B_CH    16384
#define XW_SMEM    (1024 + XW_A_BYTES + 3 * XW_B_CH)

__global__ __launch_bounds__(256) void xw_mma_kernel(const int* __restrict__ x) {
    const int t = blockIdx.y;
    if (!g_active[t]) return;

    extern __shared__ char dyn[];
    __shared__ int idxs[64];
    const uint32_t tb  = (smem_u32(dyn) + 1023u) & ~1023u;
    const uint32_t ab0 = tb;                 // A resident: 8 chunks x 8KB
    const uint32_t bb0 = tb + XW_A_BYTES;    // B: 3 x 16KB

    const int tid  = threadIdx.x;
    const int w    = tid >> 5;
    const int lane = tid & 31;
    const int n0   = blockIdx.x * 128;
    const int mw   = w >> 1;    // 0..3 (m16 tiles over M=64)
    const int nw   = w & 1;     // 0..1 (n64 halves)

    if (tid < 64) idxs[tid] = x[tid * NT + t];
    __syncthreads();

    // A resident: gather 64 e-rows (fp16), 8 k-chunks x (64 rows x 128B)
    #pragma unroll
    for (int it = 0; it < 16; it++) {
        const int o   = tid + 256 * it;   // 0..4095
        const int ach = o >> 9;           // 0..7
        const int row = (o >> 3) & 63;
        const int cb  = o & 7;
        uint32_t off = (uint32_t)(row * 128 + cb * 16);
        uint32_t sw  = off ^ ((off >> 3) & 0x70);
        cp_async16(ab0 + ach * 8192 + sw,
                   g_Ef16 + (size_t)idxs[row] * EMBD + ach * 64 + cb * 8);
    }
    CP_COMMIT();

    auto load_b = [&](int ch, int slot) {
        const uint32_t bb = bb0 + slot * XW_B_CH;
        const __half* Bsrc = ((ch < 8) ? g_WThi : g_WTlo)
                             + (size_t)n0 * EMBD + (ch & 7) * 64;
        #pragma unroll
        for (int r = 0; r < 4; r++) {
            const int o   = tid + 256 * r;   // 0..1023
            const int row = o >> 3;          // 0..127
            const int cb  = o & 7;
            uint32_t off = (uint32_t)(row * 128 + cb * 16);
            uint32_t sw  = off ^ ((off >> 3) & 0x70);
            cp_async16(bb + sw, Bsrc + (size_t)row * EMBD + cb * 8);
        }
        CP_COMMIT();
    };

    load_b(0, 0);
    load_b(1, 1);

    float c[4][2][4];
    #pragma unroll
    for (int i = 0; i < 4; i++)
        #pragma unroll
        for (int h = 0; h < 2; h++)
            #pragma unroll
            for (int r = 0; r < 4; r++) c[i][h][r] = 0.f;

    const int lrow = ((lane >> 3) & 1) * 8 + (lane & 7);
    const int lcolb = (lane >> 4) * 16;

    for (int ch = 0; ch < 16; ch++) {
        if (ch + 1 < 16) asm volatile("cp.async.wait_group 1;" ::: "memory");
        else             asm volatile("cp.async.wait_group 0;" ::: "memory");
        __syncthreads();
        if (ch + 2 < 16) load_b(ch + 2, (ch + 2) % 3);

        const uint32_t ab = ab0 + (ch & 7) * 8192;
        const uint32_t bb = bb0 + (ch % 3) * XW_B_CH;

        #pragma unroll
        for (int kk = 0; kk < 4; kk++) {
            uint32_t aoff = (uint32_t)((mw * 16 + lrow) * 128 + kk * 32 + lcolb);
            uint32_t aaddr = ab + (aoff ^ ((aoff >> 3) & 0x70));
            uint32_t a0, a1, a2, a3;
            ldsm_x4(a0, a1, a2, a3, aaddr);
            #pragma unroll
            for (int nt = 0; nt < 4; nt++) {
                uint32_t boff = (uint32_t)((nw * 64 + nt * 16 + lrow) * 128 + kk * 32 + lcolb);
                uint32_t baddr = bb + (boff ^ ((boff >> 3) & 0x70));
                uint32_t b0, b1, b2, b3;
                ldsm_x4(b0, b1, b2, b3, baddr);
                mma_f16(c[nt][0], a0, a1, a2, a3, b0, b2);
                mma_f16(c[nt][1], a0, a1, a2, a3, b1, b3);
            }
        }
    }

    float* C = g_XW + (size_t)t * NB * Z4;
    #pragma unroll
    for (int nt = 0; nt < 4; nt++) {
        #pragma unroll
        for (int h = 0; h < 2; h++) {
            const int row = mw * 16 + (lane >> 2);
            const int col = n0 + nw * 64 + nt * 16 + h * 8 + (lane & 3) * 2;
            *reinterpret_cast<float2*>(C + (size_t)row * Z4 + col) =
                make_float2(c[nt][h][0], c[nt][h][1]);
            *reinterpret_cast<float2*>(C + (size_t)(row + 8) * Z4 + col) =
                make_float2(c[nt][h][2], c[nt][h][3]);
        }
    }
}

// ---------------- persistent recurrence: 2-term fp16, block-local ----------
// 128 blocks x 256 thr, 1 CTA/SM. Block owns 32 col' (= 8 hidden units).
// A = h fp16 [64][1024] streamed; B resident (Uhi | Ulo, 32 chunks x 4KB).
// z = h@Uhi + h@Ulo in separate accumulators (ILP), folded in epilogue.
#define A_BUFS   3
#define A_CHUNK  8192
#define B_BYTES  131072
#define ZB_OFF   (B_BYTES + A_BUFS * A_CHUNK)
#define CS_OFF   (ZB_OFF + 64 * 33 * 4)
#define RNN_SMEM (1024 + CS_OFF + 4096)

__global__ __launch_bounds__(256, 1) void rnn_persist(const int* __restrict__ x,
                                                      const float* __restrict__ bias) {
    extern __shared__ char dyn[];
    __shared__ int sact[NT];
    __shared__ float sbias[32];
    const uint32_t dynb = smem_u32(dyn);
    const uint32_t tb   = (dynb + 1023u) & ~1023u;   // B: 32 chunks x 4KB
    const uint32_t ab0  = tb + B_BYTES;              // A: 3 x 8KB
    char* dynal = dyn + (tb - dynb);
    float* zbuf     = (float*)(dynal + ZB_OFF);      // [64][33]
    float* cs       = (float*)(dynal + CS_OFF);      // [512]
    float* pooled_s = cs + 512;                      // [512]

    const int tid  = threadIdx.x;
    const int w    = tid >> 5;
    const int lane = tid & 31;
    const int bid  = blockIdx.x;
    const int n0   = bid * 32;     // col' slice
    const int j0   = bid * 8;      // hidden units owned
    const int mw   = w >> 1;       // 0..3 (m16 over M=64)
    const int nw   = w & 1;        // 0..1 (n16 over N=32)

    sact[tid] = g_active[tid];
    if (tid < 32) sbias[tid] = bias[(tid & 3) * RNN + j0 + (tid >> 2)];
    if (tid < 256) { cs[tid] = 0.f; cs[tid + 256] = 0.f;
                     pooled_s[tid] = 0.f; pooled_s[tid + 256] = 0.f; }

    // ---- resident B: chunks 0..15 = Uhi, 16..31 = Ulo (32 n x 64 k each) ----
    #pragma unroll
    for (int r = 0; r < 32; r++) {
        const int o  = tid + 256 * r;    // 0..8191
        const int ch = o >> 8;           // 0..31
        const int n  = (o >> 3) & 31;
        const int cb = o & 7;
        uint32_t off = (uint32_t)(n * 128 + cb * 16);
        uint32_t sw  = off ^ ((off >> 3) & 0x70);
        const __half* src =
            (ch < 16 ? g_UThi + (size_t)(n0 + n) * RNN + ch * 64
                     : g_UTlo + (size_t)(n0 + n) * RNN + (ch - 16) * 64) + cb * 8;
        cp_async16(tb + ch * 4096 + sw, src);
    }
    CP_COMMIT();
    asm volatile("cp.async.wait_group 0;" ::: "memory");
    __syncthreads();

    const int lrow = ((lane >> 3) & 1) * 8 + (lane & 7);
    const int lcolb = (lane >> 4) * 16;

    int epoch = 0;
    int rb = 0;

    for (int t = 0; t < NT; t++) {
        if (!sact[t]) continue;
        const __half* Asrc = g_H2[rb];   // [64][1024]

        float c[2][2][4];   // [term: hi/lo][n8 half][regs]
        #pragma unroll
        for (int i = 0; i < 2; i++)
            #pragma unroll
            for (int h = 0; h < 2; h++)
                #pragma unroll
                for (int r = 0; r < 4; r++) c[i][h][r] = 0.f;

        auto load_a = [&](int ch, int slot) {
            const uint32_t ab = ab0 + slot * A_CHUNK;
            #pragma unroll
            for (int r = 0; r < 2; r++) {
                const int o   = tid + 256 * r;   // 0..511
                const int row = o >> 3;          // 0..63
                const int cb  = o & 7;
                uint32_t off = (uint32_t)(row * 128 + cb * 16);
                uint32_t sw  = off ^ ((off >> 3) & 0x70);
                cp_async16(ab + sw, Asrc + (size_t)row * RNN + ch * 64 + cb * 8);
            }
            CP_COMMIT();
        };

        load_a(0, 0);
        load_a(1, 1);

        for (int ch = 0; ch < 16; ch++) {
            if (ch < 15) asm volatile("cp.async.wait_group 1;" ::: "memory");
            else         asm volatile("cp.async.wait_group 0;" ::: "memory");
            __syncthreads();
            if (ch + 2 < 16) load_a(ch + 2, (ch + 2) % A_BUFS);

            const uint32_t ab = ab0 + (ch % A_BUFS) * A_CHUNK;

            #pragma unroll
            for (int kk = 0; kk < 4; kk++) {
                uint32_t aoff = (uint32_t)((mw * 16 + lrow) * 128 + kk * 32 + lcolb);
                uint32_t aaddr = ab + (aoff ^ ((aoff >> 3) & 0x70));
                uint32_t a0, a1, a2, a3;
                ldsm_x4(a0, a1, a2, a3, aaddr);

                uint32_t boff = (uint32_t)((nw * 16 + lrow) * 128 + kk * 32 + lcolb);
                uint32_t bsw  = boff ^ ((boff >> 3) & 0x70);
                uint32_t b0, b1, b2, b3, d0, d1, d2, d3;
                ldsm_x4(b0, b1, b2, b3, tb + ch * 4096 + bsw);          // Uhi
                ldsm_x4(d0, d1, d2, d3, tb + (16 + ch) * 4096 + bsw);   // Ulo

                mma_f16(c[0][0], a0, a1, a2, a3, b0, b2);
                mma_f16(c[0][1], a0, a1, a2, a3, b1, b3);
                mma_f16(c[1][0], a0, a1, a2, a3, d0, d2);
                mma_f16(c[1][1], a0, a1, a2, a3, d1, d3);
            }
        }
        __syncthreads();

        // epilogue: fold hi+lo terms -> z, in smem
        #pragma unroll
        for (int h = 0; h < 2; h++) {
            const int row = mw * 16 + (lane >> 2);
            const int col = nw * 16 + h * 8 + (lane & 3) * 2;
            zbuf[row * 33 + col]           = c[0][h][0] + c[1][h][0];
            zbuf[row * 33 + col + 1]       = c[0][h][1] + c[1][h][1];
            zbuf[(row + 8) * 33 + col]     = c[0][h][2] + c[1][h][2];
            zbuf[(row + 8) * 33 + col + 1] = c[0][h][3] + c[1][h][3];
        }
        __syncthreads();

        // block-local cell update: 512 cells (8 units x 64 batches)
        __half* hw = g_H2[rb ^ 1];
        const __half* hr = g_H2[rb];
        #pragma unroll
        for (int r = 0; r < 2; r++) {
            const int cell = r * 256 + tid;      // 0..511
            const int b  = cell >> 3;            // 0..63
            const int jl = cell & 7;             // 0..7
            const int j  = j0 + jl;

            float4 xw4 = *reinterpret_cast<const float4*>(
                g_XW + ((size_t)t * NB + b) * Z4 + (size_t)(n0 + jl * 4));
            const float zi = xw4.x + zbuf[b * 33 + jl * 4 + 0] + sbias[jl * 4 + 0];
            const float zf = xw4.y + zbuf[b * 33 + jl * 4 + 1] + sbias[jl * 4 + 1];
            const float zg = xw4.z + zbuf[b * 33 + jl * 4 + 2] + sbias[jl * 4 + 2];
            const float zo = xw4.w + zbuf[b * 33 + jl * 4 + 3] + sbias[jl * 4 + 3];

            const float si = 1.f / (1.f + expf(-zi));
            const float sf = 1.f / (1.f + expf(-zf));
            const float so = 1.f / (1.f + expf(-zo));
            const float cn = sf * cs[cell] + si * tanhf(zg);
            const float hn = so * tanhf(cn);
            const int xv = x[b * NT + t];
            if (xv != 0) {
                cs[cell] = cn;
                hw[b * RNN + j] = __float2half_rn(hn);
            } else {
                hw[b * RNN + j] = hr[b * RNN + j];
            }
            if (xv == 2) pooled_s[cell] += hn;
        }

        // ---- single grid barrier per step ----
        epoch++;
        __threadfence();
        __syncthreads();
        if (tid == 0) {
            unsigned old = atomicAdd(&g_arrive, 1u);
            if (old == 127u) {
                g_arrive = 0;
                asm volatile("st.release.gpu.global.s32 [%0], %1;"
                             :: "l"(&g_release), "r"(epoch) : "memory");
            } else {
                int v;
                do {
                    asm volatile("ld.acquire.gpu.global.s32 %0, [%1];"
                                 : "=r"(v) : "l"(&g_release) : "memory");
                } while (v < epoch);
            }
        }
        __syncthreads();
        __threadfence();

        rb ^= 1;
    }

    // write pooled out
    #pragma unroll
    for (int r = 0; r < 2; r++) {
        const int cell = r * 256 + tid;
        const int b  = cell >> 3;
        const int jl = cell & 7;
        g_pooled[b * RNN + j0 + jl] = pooled_s[cell];
    }
}

// ---------------- head -----------------------------------------------------
__global__ __launch_bounds__(128) void head_kernel(const float* __restrict__ W1,
                                                   const float* __restrict__ b1,
                                                   const float* __restrict__ W2,
                                                   const float* __restrict__ b2,
                                                   const float* __restrict__ Wc,
                                                   const float* __restrict__ bc,
                                                   float* __restrict__ out) {
    const int b = blockIdx.x;
    const int tid = threadIdx.x;
    __shared__ float sp[RNN];
    __shared__ float h1s[HIDN];
    __shared__ float h2s[HIDN];
    __shared__ float lg[NLAB];

    for (int k = tid; k < RNN; k += 128) sp[k] = g_pooled[(size_t)b * RNN + k];
    __syncthreads();

    float a = b1[tid];
    for (int k = 0; k < RNN; k++) a += sp[k] * W1[(size_t)k * HIDN + tid];
    h1s[tid] = fmaxf(a, 0.f);
    __syncthreads();

    float a2 = b2[tid];
    for (int k = 0; k < HIDN; k++) a2 += h1s[k] * W2[(size_t)k * HIDN + tid];
    h2s[tid] = fmaxf(a2, 0.f);
    __syncthreads();

    if (tid < NLAB) {
        float l = bc[tid];
        for (int k = 0; k < HIDN; k++) l += h2s[k] * Wc[(size_t)k * NLAB + tid];
        lg[tid] = l;
    }
    __syncthreads();
    if (tid == 0) {
        const float mx = fmaxf(fmaxf(lg[0], lg[1]), fmaxf(lg[2], lg[3]));
        const float e0 = expf(lg[0] - mx), e1 = expf(lg[1] - mx);
        const float e2 = expf(lg[2] - mx), e3 = expf(lg[3] - mx);
        const float sden = e0 + e1 + e2 + e3;
        out[b * 4 + 0] = e0 / sden; out[b * 4 + 1] = e1 / sden;
        out[b * 4 + 2] = e2 / sden; out[b * 4 + 3] = e3 / sden;
    }
}

// ---------------- launcher -------------------------------------------------
extern "C" void kernel_launch(void* const* d_in, const int* in_sizes, int n_in,
                              void* d_out, int out_size) {
    const int*   x    = (const int*)d_in[0];
    const float* emb  = (const float*)d_in[1];
    const float* W    = (const float*)d_in[2];
    const float* U    = (const float*)d_in[3];
    const float* bias = (const float*)d_in[4];
    const float* W1   = (const float*)d_in[5];
    const float* b1   = (const float*)d_in[6];
    const float* W2   = (const float*)d_in[7];
    const float* b2   = (const float*)d_in[8];
    const float* Wc   = (const float*)d_in[9];
    const float* bc   = (const float*)d_in[10];
    float* out = (float*)d_out;

    cudaFuncSetAttribute(xw_mma_kernel, cudaFuncAttributeMaxDynamicSharedMemorySize, XW_SMEM);
    cudaFuncSetAttribute(rnn_persist, cudaFuncAttributeMaxDynamicSharedMemorySize, RNN_SMEM);

    prep_kernel<<<1, 256>>>(x);
    zero_kernel<<<256, 256>>>();
    esplit_kernel<<<(VOCAB * EMBD) / 256, 256>>>(emb);
    upack_kernel<<<dim3(RNN / 64, Z4 / 64), 256>>>(U);
    wpack_kernel<<<dim3(EMBD / 64, Z4 / 64), 256>>>(W);
    xw_mma_kernel<<<dim3(32, NT), 256, XW_SMEM>>>(x);
    rnn_persist<<<128, 256, RNN_SMEM>>>(x, bias);
    head_kernel<<<NB, 128>>>(W1, b1, W2, b2, Wc, bc, out);
}

// round 13
// speedup vs baseline: 1.9968x; 1.1263x over previous
#include <cuda_runtime.h>
#include <cuda_fp16.h>
#include <math.h>
#include <stdint.h>

#define NB   64
#define NT   256
#define EMBD 512
#define VOCAB 32000
#define RNN  1024
#define Z4   4096
#define HIDN 128
#define NLAB 4

// Column permutation: original n = gate*1024 + j  ->  col' = j*4 + gate.
// fp16 scheme: h, e single fp16 (random per-step quantization, damps ~200x);
// U, W split hi+lo fp16 (systematic weight error ~2^-22, negligible).

// ---------------- static device scratch ----------------------------------
__device__ float g_XW[(size_t)NT * NB * Z4];            // emb[x] @ W  (col' layout)
__device__ __half g_UThi[(size_t)Z4 * RNN];             // U^T hi, [col'][k]
__device__ __half g_UTlo[(size_t)Z4 * RNN];
__device__ __half g_WThi[(size_t)Z4 * EMBD];
__device__ __half g_WTlo[(size_t)Z4 * EMBD];
__device__ __half g_Ef16[(size_t)VOCAB * EMBD];
__device__ __half g_H2[2][64 * RNN];                    // ping-pong h (fp16)
__device__ float g_pooled[NB * RNN];
__device__ int   g_active[NT];
__device__ unsigned g_arrive;
__device__ int   g_release;

// ---------------- helpers --------------------------------------------------
__device__ __forceinline__ uint32_t smem_u32(const void* p) {
    return (uint32_t)__cvta_generic_to_shared(p);
}
__device__ __forceinline__ void cp_async16(uint32_t smem_dst, const void* gsrc) {
    asm volatile("cp.async.cg.shared.global [%0], [%1], 16;" :: "r"(smem_dst), "l"(gsrc));
}
#define CP_COMMIT() asm volatile("cp.async.commit_group;" ::: "memory")

__device__ __forceinline__ void ldsm_x4(uint32_t& r0, uint32_t& r1,
                                        uint32_t& r2, uint32_t& r3, uint32_t addr) {
    asm volatile("ldmatrix.sync.aligned.m8n8.x4.shared.b16 {%0,%1,%2,%3}, [%4];"
                 : "=r"(r0), "=r"(r1), "=r"(r2), "=r"(r3) : "r"(addr));
}
__device__ __forceinline__ void mma_f16(float* c, uint32_t a0, uint32_t a1,
                                        uint32_t a2, uint32_t a3,
                                        uint32_t b0, uint32_t b1) {
    asm volatile("mma.sync.aligned.m16n8k16.row.col.f32.f16.f16.f32 "
                 "{%0,%1,%2,%3}, {%4,%5,%6,%7}, {%8,%9}, {%0,%1,%2,%3};"
                 : "+f"(c[0]), "+f"(c[1]), "+f"(c[2]), "+f"(c[3])
                 : "r"(a0), "r"(a1), "r"(a2), "r"(a3), "r"(b0), "r"(b1));
}
__device__ __forceinline__ float fsigmoid(float x) {
    return __fdividef(1.f, 1.f + __expf(-x));
}
__device__ __forceinline__ float ftanh(float x) {
    float y;
    asm("tanh.approx.f32 %0, %1;" : "=f"(y) : "f"(x));
    return y;
}

// ---------------- prep -----------------------------------------------------
__global__ void prep_kernel(const int* __restrict__ x) {
    int t = threadIdx.x;
    if (t < NT) {
        int act = 0;
        for (int b = 0; b < NB; b++) act |= (x[b * NT + t] != 0);
        g_active[t] = act;
    }
    if (t == 0) { g_arrive = 0; g_release = 0; }
}

__global__ void zero_kernel() {
    int i = blockIdx.x * blockDim.x + threadIdx.x;   // 256*256 = 65536
    ((uint32_t*)g_H2)[i] = 0u;
}

// ---------------- emb -> fp16 ------------------------------------------------
__global__ __launch_bounds__(256) void esplit_kernel(const float* __restrict__ emb) {
    size_t i = (size_t)blockIdx.x * 256 + threadIdx.x;
    g_Ef16[i] = __float2half_rn(emb[i]);
}

// ---------------- transpose+split+permute: U and W -------------------------
__device__ __forceinline__ int permute_col(int n) {
    return (n & 1023) * 4 + (n >> 10);
}

__global__ __launch_bounds__(256) void upack_kernel(const float* __restrict__ U) {
    __shared__ float tile[64][65];
    const int k0 = blockIdx.x * 64;
    const int n0 = blockIdx.y * 64;
    const int tid = threadIdx.x;
    #pragma unroll
    for (int it = 0; it < 16; it++) {
        int r = it * 4 + (tid >> 6);
        int c = tid & 63;
        tile[r][c] = U[(size_t)(k0 + r) * Z4 + n0 + c];
    }
    __syncthreads();
    #pragma unroll
    for (int it = 0; it < 16; it++) {
        int n = it * 4 + (tid >> 6);
        int k = tid & 63;
        float v = tile[k][n];
        __half hi = __float2half_rn(v);
        const int np = permute_col(n0 + n);
        g_UThi[(size_t)np * RNN + k0 + k] = hi;
        g_UTlo[(size_t)np * RNN + k0 + k] = __float2half_rn(v - __half2float(hi));
    }
}

__global__ __launch_bounds__(256) void wpack_kernel(const float* __restrict__ W) {
    __shared__ float tile[64][65];
    const int k0 = blockIdx.x * 64;
    const int n0 = blockIdx.y * 64;
    const int tid = threadIdx.x;
    #pragma unroll
    for (int it = 0; it < 16; it++) {
        int r = it * 4 + (tid >> 6);
        int c = tid & 63;
        tile[r][c] = W[(size_t)(k0 + r) * Z4 + n0 + c];
    }
    __syncthreads();
    #pragma unroll
    for (int it = 0; it < 16; it++) {
        int n = it * 4 + (tid >> 6);
        int k = tid & 63;
        float v = tile[k][n];
        __half hi = __float2half_rn(v);
        const int np = permute_col(n0 + n);
        g_WThi[(size_t)np * EMBD + k0 + k] = hi;
        g_WTlo[(size_t)np * EMBD + k0 + k] = __float2half_rn(v - __half2float(hi));
    }
}

// ---------------- fp16 input projection (unchanged from R12) ---------------
#define XW_A_BYTES 65536
#define XW_B_CH    16384
#define XW_SMEM    (1024 + XW_A_BYTES + 3 * XW_B_CH)

__global__ __launch_bounds__(256) void xw_mma_kernel(const int* __restrict__ x) {
    const int t = blockIdx.y;
    if (!g_active[t]) return;

    extern __shared__ char dyn[];
    __shared__ int idxs[64];
    const uint32_t tb  = (smem_u32(dyn) + 1023u) & ~1023u;
    const uint32_t ab0 = tb;
    const uint32_t bb0 = tb + XW_A_BYTES;

    const int tid  = threadIdx.x;
    const int w    = tid >> 5;
    const int lane = tid & 31;
    const int n0   = blockIdx.x * 128;
    const int mw   = w >> 1;
    const int nw   = w & 1;

    if (tid < 64) idxs[tid] = x[tid * NT + t];
    __syncthreads();

    #pragma unroll
    for (int it = 0; it < 16; it++) {
        const int o   = tid + 256 * it;
        const int ach = o >> 9;
        const int row = (o >> 3) & 63;
        const int cb  = o & 7;
        uint32_t off = (uint32_t)(row * 128 + cb * 16);
        uint32_t sw  = off ^ ((off >> 3) & 0x70);
        cp_async16(ab0 + ach * 8192 + sw,
                   g_Ef16 + (size_t)idxs[row] * EMBD + ach * 64 + cb * 8);
    }
    CP_COMMIT();

    auto load_b = [&](int ch, int slot) {
        const uint32_t bb = bb0 + slot * XW_B_CH;
        const __half* Bsrc = ((ch < 8) ? g_WThi : g_WTlo)
                             + (size_t)n0 * EMBD + (ch & 7) * 64;
        #pragma unroll
        for (int r = 0; r < 4; r++) {
            const int o   = tid + 256 * r;
            const int row = o >> 3;
            const int cb  = o & 7;
            uint32_t off = (uint32_t)(row * 128 + cb * 16);
            uint32_t sw  = off ^ ((off >> 3) & 0x70);
            cp_async16(bb + sw, Bsrc + (size_t)row * EMBD + cb * 8);
        }
        CP_COMMIT();
    };

    load_b(0, 0);
    load_b(1, 1);

    float c[4][2][4];
    #pragma unroll
    for (int i = 0; i < 4; i++)
        #pragma unroll
        for (int h = 0; h < 2; h++)
            #pragma unroll
            for (int r = 0; r < 4; r++) c[i][h][r] = 0.f;

    const int lrow = ((lane >> 3) & 1) * 8 + (lane & 7);
    const int lcolb = (lane >> 4) * 16;

    for (int ch = 0; ch < 16; ch++) {
        if (ch + 1 < 16) asm volatile("cp.async.wait_group 1;" ::: "memory");
        else             asm volatile("cp.async.wait_group 0;" ::: "memory");
        __syncthreads();
        if (ch + 2 < 16) load_b(ch + 2, (ch + 2) % 3);

        const uint32_t ab = ab0 + (ch & 7) * 8192;
        const uint32_t bb = bb0 + (ch % 3) * XW_B_CH;

        #pragma unroll
        for (int kk = 0; kk < 4; kk++) {
            uint32_t aoff = (uint32_t)((mw * 16 + lrow) * 128 + kk * 32 + lcolb);
            uint32_t aaddr = ab + (aoff ^ ((aoff >> 3) & 0x70));
            uint32_t a0, a1, a2, a3;
            ldsm_x4(a0, a1, a2, a3, aaddr);
            #pragma unroll
            for (int nt = 0; nt < 4; nt++) {
                uint32_t boff = (uint32_t)((nw * 64 + nt * 16 + lrow) * 128 + kk * 32 + lcolb);
                uint32_t baddr = bb + (boff ^ ((boff >> 3) & 0x70));
                uint32_t b0, b1, b2, b3;
                ldsm_x4(b0, b1, b2, b3, baddr);
                mma_f16(c[nt][0], a0, a1, a2, a3, b0, b2);
                mma_f16(c[nt][1], a0, a1, a2, a3, b1, b3);
            }
        }
    }

    float* C = g_XW + (size_t)t * NB * Z4;
    #pragma unroll
    for (int nt = 0; nt < 4; nt++) {
        #pragma unroll
        for (int h = 0; h < 2; h++) {
            const int row = mw * 16 + (lane >> 2);
            const int col = n0 + nw * 64 + nt * 16 + h * 8 + (lane & 3) * 2;
            *reinterpret_cast<float2*>(C + (size_t)row * Z4 + col) =
                make_float2(c[nt][h][0], c[nt][h][1]);
            *reinterpret_cast<float2*>(C + (size_t)(row + 8) * Z4 + col) =
                make_float2(c[nt][h][2], c[nt][h][3]);
        }
    }
}

// ---------------- persistent recurrence: K=128 chunks, XW prefetch ---------
// 128 blocks x 256 thr. Block owns 32 col' (8 hidden units), all 64 batches.
// B resident (Uhi|Ulo, 32 x 4KB k64-chunks). A = h fp16 streamed in 8 chunks
// of K=128 (2 sub-tiles of 8KB each). XW tile prefetched with chunk 0.
#define A_BUFS   3
#define A_CHUNK  16384
#define B_BYTES  131072
#define XW_OFF   (B_BYTES + A_BUFS * A_CHUNK)
#define ZB_OFF   (XW_OFF + 8192)
#define CS_OFF   (ZB_OFF + 64 * 33 * 4)
#define RNN_SMEM (1024 + CS_OFF + 4096)

__global__ __launch_bounds__(256, 1) void rnn_persist(const int* __restrict__ x,
                                                      const float* __restrict__ bias) {
    extern __shared__ char dyn[];
    __shared__ int sact[NT];
    __shared__ float sbias[32];
    const uint32_t dynb = smem_u32(dyn);
    const uint32_t tb   = (dynb + 1023u) & ~1023u;
    const uint32_t ab0  = tb + B_BYTES;
    const uint32_t xwsm = tb + XW_OFF;
    char* dynal = dyn + (tb - dynb);
    float* xws      = (float*)(dynal + XW_OFF);      // [512] float4
    float* zbuf     = (float*)(dynal + ZB_OFF);      // [64][33]
    float* cs       = (float*)(dynal + CS_OFF);      // [512]
    float* pooled_s = cs + 512;                      // [512]

    const int tid  = threadIdx.x;
    const int w    = tid >> 5;
    const int lane = tid & 31;
    const int bid  = blockIdx.x;
    const int n0   = bid * 32;
    const int j0   = bid * 8;
    const int mw   = w >> 1;       // 0..3 (m16 over M=64)
    const int nw   = w & 1;        // 0..1 (n16 over N=32)

    sact[tid] = g_active[tid];
    if (tid < 32) sbias[tid] = bias[(tid & 3) * RNN + j0 + (tid >> 2)];
    if (tid < 256) { cs[tid] = 0.f; cs[tid + 256] = 0.f;
                     pooled_s[tid] = 0.f; pooled_s[tid + 256] = 0.f; }

    // ---- resident B: chunks 0..15 = Uhi, 16..31 = Ulo (32 n x 64 k each) ----
    #pragma unroll
    for (int r = 0; r < 32; r++) {
        const int o  = tid + 256 * r;
        const int ch = o >> 8;
        const int n  = (o >> 3) & 31;
        const int cb = o & 7;
        uint32_t off = (uint32_t)(n * 128 + cb * 16);
        uint32_t sw  = off ^ ((off >> 3) & 0x70);
        const __half* src =
            (ch < 16 ? g_UThi + (size_t)(n0 + n) * RNN + ch * 64
                     : g_UTlo + (size_t)(n0 + n) * RNN + (ch - 16) * 64) + cb * 8;
        cp_async16(tb + ch * 4096 + sw, src);
    }
    CP_COMMIT();
    asm volatile("cp.async.wait_group 0;" ::: "memory");
    __syncthreads();

    const int lrow = ((lane >> 3) & 1) * 8 + (lane & 7);
    const int lcolb = (lane >> 4) * 16;

    int epoch = 0;
    int rb = 0;

    for (int t = 0; t < NT; t++) {
        if (!sact[t]) continue;
        const __half* Asrc = g_H2[rb];   // [64][1024]

        float c[2][2][4];   // [term: hi/lo][n8 half][regs]
        #pragma unroll
        for (int i = 0; i < 2; i++)
            #pragma unroll
            for (int h = 0; h < 2; h++)
                #pragma unroll
                for (int r = 0; r < 4; r++) c[i][h][r] = 0.f;

        // A chunk = K=128: two 8KB sub-tiles (k 0-63, 64-127)
        auto load_a_ops = [&](int ch, int slot) {
            const uint32_t ab = ab0 + slot * A_CHUNK;
            #pragma unroll
            for (int r = 0; r < 4; r++) {
                const int o   = tid + 256 * r;   // 0..1023
                const int sub = o >> 9;          // 0..1
                const int row = (o >> 3) & 63;
                const int cb  = o & 7;
                uint32_t off = (uint32_t)(row * 128 + cb * 16);
                uint32_t sw  = off ^ ((off >> 3) & 0x70);
                cp_async16(ab + sub * 8192 + sw,
                           Asrc + (size_t)row * RNN + ch * 128 + sub * 64 + cb * 8);
            }
        };

        // chunk 0 + XW prefetch share group 0
        load_a_ops(0, 0);
        {
            #pragma unroll
            for (int r = 0; r < 2; r++) {
                const int cell = r * 256 + tid;   // 0..511
                const int b  = cell >> 3;
                const int jl = cell & 7;
                cp_async16(xwsm + cell * 16,
                           g_XW + ((size_t)t * NB + b) * Z4 + (size_t)(n0 + jl * 4));
            }
        }
        CP_COMMIT();
        load_a_ops(1, 1);
        CP_COMMIT();

        for (int ch = 0; ch < 8; ch++) {
            if (ch < 7) asm volatile("cp.async.wait_group 1;" ::: "memory");
            else        asm volatile("cp.async.wait_group 0;" ::: "memory");
            __syncthreads();
            if (ch + 2 < 8) { load_a_ops(ch + 2, (ch + 2) % A_BUFS); CP_COMMIT(); }

            const uint32_t ab = ab0 + (ch % A_BUFS) * A_CHUNK;

            #pragma unroll
            for (int kk = 0; kk < 8; kk++) {
                const int sub = kk >> 2;
                const int k4  = kk & 3;
                uint32_t aoff = (uint32_t)((mw * 16 + lrow) * 128 + k4 * 32 + lcolb);
                uint32_t aaddr = ab + sub * 8192 + (aoff ^ ((aoff >> 3) & 0x70));
                uint32_t a0, a1, a2, a3;
                ldsm_x4(a0, a1, a2, a3, aaddr);

                const int bch = ch * 2 + sub;    // k64-chunk index 0..15
                uint32_t boff = (uint32_t)((nw * 16 + lrow) * 128 + k4 * 32 + lcolb);
                uint32_t bsw  = boff ^ ((boff >> 3) & 0x70);
                uint32_t b0, b1, b2, b3, d0, d1, d2, d3;
                ldsm_x4(b0, b1, b2, b3, tb + bch * 4096 + bsw);          // Uhi
                ldsm_x4(d0, d1, d2, d3, tb + (16 + bch) * 4096 + bsw);   // Ulo

                mma_f16(c[0][0], a0, a1, a2, a3, b0, b2);
                mma_f16(c[0][1], a0, a1, a2, a3, b1, b3);
                mma_f16(c[1][0], a0, a1, a2, a3, d0, d2);
                mma_f16(c[1][1], a0, a1, a2, a3, d1, d3);
            }
        }
        __syncthreads();

        // epilogue: fold hi+lo terms -> z, in smem
        #pragma unroll
        for (int h = 0; h < 2; h++) {
            const int row = mw * 16 + (lane >> 2);
            const int col = nw * 16 + h * 8 + (lane & 3) * 2;
            zbuf[row * 33 + col]           = c[0][h][0] + c[1][h][0];
            zbuf[row * 33 + col + 1]       = c[0][h][1] + c[1][h][1];
            zbuf[(row + 8) * 33 + col]     = c[0][h][2] + c[1][h][2];
            zbuf[(row + 8) * 33 + col + 1] = c[0][h][3] + c[1][h][3];
        }
        __syncthreads();

        // block-local cell update: 512 cells (8 units x 64 batches)
        __half* hw = g_H2[rb ^ 1];
        const __half* hr = g_H2[rb];
        #pragma unroll
        for (int r = 0; r < 2; r++) {
            const int cell = r * 256 + tid;
            const int b  = cell >> 3;
            const int jl = cell & 7;
            const int j  = j0 + jl;

            float4 xw4 = *reinterpret_cast<const float4*>(xws + cell * 4);
            const float zi = xw4.x + zbuf[b * 33 + jl * 4 + 0] + sbias[jl * 4 + 0];
            const float zf = xw4.y + zbuf[b * 33 + jl * 4 + 1] + sbias[jl * 4 + 1];
            const float zg = xw4.z + zbuf[b * 33 + jl * 4 + 2] + sbias[jl * 4 + 2];
            const float zo = xw4.w + zbuf[b * 33 + jl * 4 + 3] + sbias[jl * 4 + 3];

            const float si = fsigmoid(zi);
            const float sf = fsigmoid(zf);
            const float so = fsigmoid(zo);
            const float cn = sf * cs[cell] + si * ftanh(zg);
            const float hn = so * ftanh(cn);
            const int xv = x[b * NT + t];
            if (xv != 0) {
                cs[cell] = cn;
                hw[b * RNN + j] = __float2half_rn(hn);
            } else {
                hw[b * RNN + j] = hr[b * RNN + j];
            }
            if (xv == 2) pooled_s[cell] += hn;
        }

        // ---- single grid barrier per step ----
        epoch++;
        __threadfence();
        __syncthreads();
        if (tid == 0) {
            unsigned old = atomicAdd(&g_arrive, 1u);
            if (old == 127u) {
                g_arrive = 0;
                asm volatile("st.release.gpu.global.s32 [%0], %1;"
                             :: "l"(&g_release), "r"(epoch) : "memory");
            } else {
                int v;
                do {
                    asm volatile("ld.acquire.gpu.global.s32 %0, [%1];"
                                 : "=r"(v) : "l"(&g_release) : "memory");
                } while (v < epoch);
            }
        }
        __syncthreads();
        __threadfence();

        rb ^= 1;
    }

    // write pooled out
    #pragma unroll
    for (int r = 0; r < 2; r++) {
        const int cell = r * 256 + tid;
        const int b  = cell >> 3;
        const int jl = cell & 7;
        g_pooled[b * RNN + j0 + jl] = pooled_s[cell];
    }
}

// ---------------- head (precise math; errors here don't damp) --------------
__global__ __launch_bounds__(128) void head_kernel(const float* __restrict__ W1,
                                                   const float* __restrict__ b1,
                                                   const float* __restrict__ W2,
                                                   const float* __restrict__ b2,
                                                   const float* __restrict__ Wc,
                                                   const float* __restrict__ bc,
                                                   float* __restrict__ out) {
    const int b = blockIdx.x;
    const int tid = threadIdx.x;
    __shared__ float sp[RNN];
    __shared__ float h1s[HIDN];
    __shared__ float h2s[HIDN];
    __shared__ float lg[NLAB];

    for (int k = tid; k < RNN; k += 128) sp[k] = g_pooled[(size_t)b * RNN + k];
    __syncthreads();

    float a = b1[tid];
    for (int k = 0; k < RNN; k++) a += sp[k] * W1[(size_t)k * HIDN + tid];
    h1s[tid] = fmaxf(a, 0.f);
    __syncthreads();

    float a2 = b2[tid];
    for (int k = 0; k < HIDN; k++) a2 += h1s[k] * W2[(size_t)k * HIDN + tid];
    h2s[tid] = fmaxf(a2, 0.f);
    __syncthreads();

    if (tid < NLAB) {
        float l = bc[tid];
        for (int k = 0; k < HIDN; k++) l += h2s[k] * Wc[(size_t)k * NLAB + tid];
        lg[tid] = l;
    }
    __syncthreads();
    if (tid == 0) {
        const float mx = fmaxf(fmaxf(lg[0], lg[1]), fmaxf(lg[2], lg[3]));
        const float e0 = expf(lg[0] - mx), e1 = expf(lg[1] - mx);
        const float e2 = expf(lg[2] - mx), e3 = expf(lg[3] - mx);
        const float sden = e0 + e1 + e2 + e3;
        out[b * 4 + 0] = e0 / sden; out[b * 4 + 1] = e1 / sden;
        out[b * 4 + 2] = e2 / sden; out[b * 4 + 3] = e3 / sden;
    }
}

// ---------------- launcher -------------------------------------------------
extern "C" void kernel_launch(void* const* d_in, const int* in_sizes, int n_in,
                              void* d_out, int out_size) {
    const int*   x    = (const int*)d_in[0];
    const float* emb  = (const float*)d_in[1];
    const float* W    = (const float*)d_in[2];
    const float* U    = (const float*)d_in[3];
    const float* bias = (const float*)d_in[4];
    const float* W1   = (const float*)d_in[5];
    const float* b1   = (const float*)d_in[6];
    const float* W2   = (const float*)d_in[7];
    const float* b2   = (const float*)d_in[8];
    const float* Wc   = (const float*)d_in[9];
    const float* bc   = (const float*)d_in[10];
    float* out = (float*)d_out;

    cudaFuncSetAttribute(xw_mma_kernel, cudaFuncAttributeMaxDynamicSharedMemorySize, XW_SMEM);
    cudaFuncSetAttribute(rnn_persist, cudaFuncAttributeMaxDynamicSharedMemorySize, RNN_SMEM);

    prep_kernel<<<1, 256>>>(x);
    zero_kernel<<<256, 256>>>();
    esplit_kernel<<<(VOCAB * EMBD) / 256, 256>>>(emb);
    upack_kernel<<<dim3(RNN / 64, Z4 / 64), 256>>>(U);
    wpack_kernel<<<dim3(EMBD / 64, Z4 / 64), 256>>>(W);
    xw_mma_kernel<<<dim3(32, NT), 256, XW_SMEM>>>(x);
    rnn_persist<<<128, 256, RNN_SMEM>>>(x, bias);
    head_kernel<<<NB, 128>>>(W1, b1, W2, b2, Wc, bc, out);
}

// round 14
// speedup vs baseline: 2.2432x; 1.1234x over previous
#include <cuda_runtime.h>
#include <cuda_fp16.h>
#include <math.h>
#include <stdint.h>

#define NB   64
#define NT   256
#define EMBD 512
#define VOCAB 32000
#define RNN  1024
#define Z4   4096
#define HIDN 128
#define NLAB 4

// Column permutation: original n = gate*1024 + j  ->  col' = j*4 + gate.
// fp16 scheme: h, e single fp16 (random per-step quantization, damps ~200x);
// U, W split hi+lo fp16 (systematic weight error ~2^-22, negligible).

// ---------------- static device scratch ----------------------------------
__device__ float g_XW[(size_t)NT * NB * Z4];            // emb[x] @ W  (col' layout)
__device__ __half g_UThi[(size_t)Z4 * RNN];             // U^T hi, [col'][k]
__device__ __half g_UTlo[(size_t)Z4 * RNN];
__device__ __half g_WThi[(size_t)Z4 * EMBD];
__device__ __half g_WTlo[(size_t)Z4 * EMBD];
__device__ __half g_Ef16[(size_t)VOCAB * EMBD];
__device__ __half g_H2[2][64 * RNN];                    // ping-pong h (fp16)
__device__ float g_pooled[NB * RNN];
__device__ int   g_active[NT];
__device__ unsigned g_arrive;
__device__ int   g_release;

// ---------------- helpers --------------------------------------------------
__device__ __forceinline__ uint32_t smem_u32(const void* p) {
    return (uint32_t)__cvta_generic_to_shared(p);
}
__device__ __forceinline__ void cp_async16(uint32_t smem_dst, const void* gsrc) {
    asm volatile("cp.async.cg.shared.global [%0], [%1], 16;" :: "r"(smem_dst), "l"(gsrc));
}
#define CP_COMMIT() asm volatile("cp.async.commit_group;" ::: "memory")

__device__ __forceinline__ void ldsm_x4(uint32_t& r0, uint32_t& r1,
                                        uint32_t& r2, uint32_t& r3, uint32_t addr) {
    asm volatile("ldmatrix.sync.aligned.m8n8.x4.shared.b16 {%0,%1,%2,%3}, [%4];"
                 : "=r"(r0), "=r"(r1), "=r"(r2), "=r"(r3) : "r"(addr));
}
__device__ __forceinline__ void mma_f16(float* c, uint32_t a0, uint32_t a1,
                                        uint32_t a2, uint32_t a3,
                                        uint32_t b0, uint32_t b1) {
    asm volatile("mma.sync.aligned.m16n8k16.row.col.f32.f16.f16.f32 "
                 "{%0,%1,%2,%3}, {%4,%5,%6,%7}, {%8,%9}, {%0,%1,%2,%3};"
                 : "+f"(c[0]), "+f"(c[1]), "+f"(c[2]), "+f"(c[3])
                 : "r"(a0), "r"(a1), "r"(a2), "r"(a3), "r"(b0), "r"(b1));
}
__device__ __forceinline__ float fsigmoid(float x) {
    return __fdividef(1.f, 1.f + __expf(-x));
}
__device__ __forceinline__ float ftanh(float x) {
    float y;
    asm("tanh.approx.f32 %0, %1;" : "=f"(y) : "f"(x));
    return y;
}

// ---------------- prep -----------------------------------------------------
__global__ void prep_kernel(const int* __restrict__ x) {
    int t = threadIdx.x;
    if (t < NT) {
        int act = 0;
        for (int b = 0; b < NB; b++) act |= (x[b * NT + t] != 0);
        g_active[t] = act;
    }
    if (t == 0) { g_arrive = 0; g_release = 0; }
}

__global__ void zero_kernel() {
    int i = blockIdx.x * blockDim.x + threadIdx.x;
    ((uint32_t*)g_H2)[i] = 0u;
}

// ---------------- emb -> fp16 ------------------------------------------------
__global__ __launch_bounds__(256) void esplit_kernel(const float* __restrict__ emb) {
    size_t i = (size_t)blockIdx.x * 256 + threadIdx.x;
    g_Ef16[i] = __float2half_rn(emb[i]);
}

// ---------------- transpose+split+permute: U and W -------------------------
__device__ __forceinline__ int permute_col(int n) {
    return (n & 1023) * 4 + (n >> 10);
}

__global__ __launch_bounds__(256) void upack_kernel(const float* __restrict__ U) {
    __shared__ float tile[64][65];
    const int k0 = blockIdx.x * 64;
    const int n0 = blockIdx.y * 64;
    const int tid = threadIdx.x;
    #pragma unroll
    for (int it = 0; it < 16; it++) {
        int r = it * 4 + (tid >> 6);
        int c = tid & 63;
        tile[r][c] = U[(size_t)(k0 + r) * Z4 + n0 + c];
    }
    __syncthreads();
    #pragma unroll
    for (int it = 0; it < 16; it++) {
        int n = it * 4 + (tid >> 6);
        int k = tid & 63;
        float v = tile[k][n];
        __half hi = __float2half_rn(v);
        const int np = permute_col(n0 + n);
        g_UThi[(size_t)np * RNN + k0 + k] = hi;
        g_UTlo[(size_t)np * RNN + k0 + k] = __float2half_rn(v - __half2float(hi));
    }
}

__global__ __launch_bounds__(256) void wpack_kernel(const float* __restrict__ W) {
    __shared__ float tile[64][65];
    const int k0 = blockIdx.x * 64;
    const int n0 = blockIdx.y * 64;
    const int tid = threadIdx.x;
    #pragma unroll
    for (int it = 0; it < 16; it++) {
        int r = it * 4 + (tid >> 6);
        int c = tid & 63;
        tile[r][c] = W[(size_t)(k0 + r) * Z4 + n0 + c];
    }
    __syncthreads();
    #pragma unroll
    for (int it = 0; it < 16; it++) {
        int n = it * 4 + (tid >> 6);
        int k = tid & 63;
        float v = tile[k][n];
        __half hi = __float2half_rn(v);
        const int np = permute_col(n0 + n);
        g_WThi[(size_t)np * EMBD + k0 + k] = hi;
        g_WTlo[(size_t)np * EMBD + k0 + k] = __float2half_rn(v - __half2float(hi));
    }
}

// ---------------- fp16 input projection: 2 timesteps per block -------------
// grid (32 n-tiles, 128 t-pairs) x 256. M=128 = [e(t0) 64 rows; e(t1) 64 rows],
// A resident in smem (8 k-chunks x 16KB). B streamed 16 chunks
// (pass0 Whi, pass1 Wlo), accumulated -> exact e @ (Whi+Wlo) per t.
#define XW_A_BYTES 131072
#define XW_B_CH    16384
#define XW_SMEM    (1024 + XW_A_BYTES + 3 * XW_B_CH)

__global__ __launch_bounds__(256) void xw_mma_kernel(const int* __restrict__ x) {
    const int t0 = blockIdx.y * 2;
    const int t1 = t0 + 1;
    const int a0t = g_active[t0];
    const int a1t = g_active[t1];
    if (!a0t && !a1t) return;

    extern __shared__ char dyn[];
    __shared__ int idxs[128];
    const uint32_t tb  = (smem_u32(dyn) + 1023u) & ~1023u;
    const uint32_t ab0 = tb;
    const uint32_t bb0 = tb + XW_A_BYTES;

    const int tid  = threadIdx.x;
    const int w    = tid >> 5;
    const int lane = tid & 31;
    const int n0   = blockIdx.x * 128;
    const int mw   = w >> 1;    // 0..3
    const int nw   = w & 1;     // 0..1

    if (tid < 64)        idxs[tid] = x[tid * NT + t0];
    else if (tid < 128)  idxs[tid] = x[(tid - 64) * NT + t1];
    __syncthreads();

    // A resident: 128 gathered e-rows, 8 k-chunks x (128 rows x 128B)
    #pragma unroll
    for (int it = 0; it < 32; it++) {
        const int o   = tid + 256 * it;   // 0..8191
        const int ach = o >> 10;          // 0..7
        const int row = (o >> 3) & 127;
        const int cb  = o & 7;
        uint32_t off = (uint32_t)(row * 128 + cb * 16);
        uint32_t sw  = off ^ ((off >> 3) & 0x70);
        cp_async16(ab0 + ach * 16384 + sw,
                   g_Ef16 + (size_t)idxs[row] * EMBD + ach * 64 + cb * 8);
    }
    CP_COMMIT();

    auto load_b = [&](int ch, int slot) {
        const uint32_t bb = bb0 + slot * XW_B_CH;
        const __half* Bsrc = ((ch < 8) ? g_WThi : g_WTlo)
                             + (size_t)n0 * EMBD + (ch & 7) * 64;
        #pragma unroll
        for (int r = 0; r < 4; r++) {
            const int o   = tid + 256 * r;
            const int row = o >> 3;
            const int cb  = o & 7;
            uint32_t off = (uint32_t)(row * 128 + cb * 16);
            uint32_t sw  = off ^ ((off >> 3) & 0x70);
            cp_async16(bb + sw, Bsrc + (size_t)row * EMBD + cb * 8);
        }
        CP_COMMIT();
    };

    load_b(0, 0);
    load_b(1, 1);

    float c[2][4][2][4];   // [t: 0/1][nt][n8 half][regs]
    #pragma unroll
    for (int i = 0; i < 2; i++)
        #pragma unroll
        for (int j = 0; j < 4; j++)
            #pragma unroll
            for (int h = 0; h < 2; h++)
                #pragma unroll
                for (int r = 0; r < 4; r++) c[i][j][h][r] = 0.f;

    const int lrow = ((lane >> 3) & 1) * 8 + (lane & 7);
    const int lcolb = (lane >> 4) * 16;

    for (int ch = 0; ch < 16; ch++) {
        if (ch + 1 < 16) asm volatile("cp.async.wait_group 1;" ::: "memory");
        else             asm volatile("cp.async.wait_group 0;" ::: "memory");
        __syncthreads();
        if (ch + 2 < 16) load_b(ch + 2, (ch + 2) % 3);

        const uint32_t ab = ab0 + (ch & 7) * 16384;
        const uint32_t bb = bb0 + (ch % 3) * XW_B_CH;

        #pragma unroll
        for (int kk = 0; kk < 4; kk++) {
            uint32_t bf[4][4];
            #pragma unroll
            for (int nt = 0; nt < 4; nt++) {
                uint32_t boff = (uint32_t)((nw * 64 + nt * 16 + lrow) * 128 + kk * 32 + lcolb);
                uint32_t baddr = bb + (boff ^ ((boff >> 3) & 0x70));
                ldsm_x4(bf[nt][0], bf[nt][1], bf[nt][2], bf[nt][3], baddr);
            }
            #pragma unroll
            for (int mt = 0; mt < 2; mt++) {
                const int mbase = mt * 64 + mw * 16;
                uint32_t aoff = (uint32_t)((mbase + lrow) * 128 + kk * 32 + lcolb);
                uint32_t aaddr = ab + (aoff ^ ((aoff >> 3) & 0x70));
                uint32_t a0, a1, a2, a3;
                ldsm_x4(a0, a1, a2, a3, aaddr);
                #pragma unroll
                for (int nt = 0; nt < 4; nt++) {
                    mma_f16(c[mt][nt][0], a0, a1, a2, a3, bf[nt][0], bf[nt][2]);
                    mma_f16(c[mt][nt][1], a0, a1, a2, a3, bf[nt][1], bf[nt][3]);
                }
            }
        }
        __syncthreads();
    }

    #pragma unroll
    for (int mt = 0; mt < 2; mt++) {
        if (!(mt ? a1t : a0t)) continue;
        float* C = g_XW + (size_t)(mt ? t1 : t0) * NB * Z4;
        #pragma unroll
        for (int nt = 0; nt < 4; nt++) {
            #pragma unroll
            for (int h = 0; h < 2; h++) {
                const int row = mw * 16 + (lane >> 2);
                const int col = n0 + nw * 64 + nt * 16 + h * 8 + (lane & 3) * 2;
                *reinterpret_cast<float2*>(C + (size_t)row * Z4 + col) =
                    make_float2(c[mt][nt][h][0], c[mt][nt][h][1]);
                *reinterpret_cast<float2*>(C + (size_t)(row + 8) * Z4 + col) =
                    make_float2(c[mt][nt][h][2], c[mt][nt][h][3]);
            }
        }
    }
}

// ---------------- persistent recurrence (fence-free barrier) ---------------
#define A_BUFS   3
#define A_CHUNK  16384
#define B_BYTES  131072
#define XW_OFF   (B_BYTES + A_BUFS * A_CHUNK)
#define ZB_OFF   (XW_OFF + 8192)
#define CS_OFF   (ZB_OFF + 64 * 33 * 4)
#define RNN_SMEM (1024 + CS_OFF + 4096)

__global__ __launch_bounds__(256, 1) void rnn_persist(const int* __restrict__ x,
                                                      const float* __restrict__ bias) {
    extern __shared__ char dyn[];
    __shared__ int sact[NT];
    __shared__ float sbias[32];
    const uint32_t dynb = smem_u32(dyn);
    const uint32_t tb   = (dynb + 1023u) & ~1023u;
    const uint32_t ab0  = tb + B_BYTES;
    const uint32_t xwsm = tb + XW_OFF;
    char* dynal = dyn + (tb - dynb);
    float* xws      = (float*)(dynal + XW_OFF);
    float* zbuf     = (float*)(dynal + ZB_OFF);
    float* cs       = (float*)(dynal + CS_OFF);
    float* pooled_s = cs + 512;

    const int tid  = threadIdx.x;
    const int w    = tid >> 5;
    const int lane = tid & 31;
    const int bid  = blockIdx.x;
    const int n0   = bid * 32;
    const int j0   = bid * 8;
    const int mw   = w >> 1;
    const int nw   = w & 1;

    sact[tid] = g_active[tid];
    if (tid < 32) sbias[tid] = bias[(tid & 3) * RNN + j0 + (tid >> 2)];
    if (tid < 256) { cs[tid] = 0.f; cs[tid + 256] = 0.f;
                     pooled_s[tid] = 0.f; pooled_s[tid + 256] = 0.f; }

    // resident B: chunks 0..15 = Uhi, 16..31 = Ulo
    #pragma unroll
    for (int r = 0; r < 32; r++) {
        const int o  = tid + 256 * r;
        const int ch = o >> 8;
        const int n  = (o >> 3) & 31;
        const int cb = o & 7;
        uint32_t off = (uint32_t)(n * 128 + cb * 16);
        uint32_t sw  = off ^ ((off >> 3) & 0x70);
        const __half* src =
            (ch < 16 ? g_UThi + (size_t)(n0 + n) * RNN + ch * 64
                     : g_UTlo + (size_t)(n0 + n) * RNN + (ch - 16) * 64) + cb * 8;
        cp_async16(tb + ch * 4096 + sw, src);
    }
    CP_COMMIT();
    asm volatile("cp.async.wait_group 0;" ::: "memory");
    __syncthreads();

    const int lrow = ((lane >> 3) & 1) * 8 + (lane & 7);
    const int lcolb = (lane >> 4) * 16;

    int epoch = 0;
    int rb = 0;

    for (int t = 0; t < NT; t++) {
        if (!sact[t]) continue;
        const __half* Asrc = g_H2[rb];

        float c[2][2][4];
        #pragma unroll
        for (int i = 0; i < 2; i++)
            #pragma unroll
            for (int h = 0; h < 2; h++)
                #pragma unroll
                for (int r = 0; r < 4; r++) c[i][h][r] = 0.f;

        auto load_a_ops = [&](int ch, int slot) {
            const uint32_t ab = ab0 + slot * A_CHUNK;
            #pragma unroll
            for (int r = 0; r < 4; r++) {
                const int o   = tid + 256 * r;
                const int sub = o >> 9;
                const int row = (o >> 3) & 63;
                const int cb  = o & 7;
                uint32_t off = (uint32_t)(row * 128 + cb * 16);
                uint32_t sw  = off ^ ((off >> 3) & 0x70);
                cp_async16(ab + sub * 8192 + sw,
                           Asrc + (size_t)row * RNN + ch * 128 + sub * 64 + cb * 8);
            }
        };

        load_a_ops(0, 0);
        {
            #pragma unroll
            for (int r = 0; r < 2; r++) {
                const int cell = r * 256 + tid;
                const int b  = cell >> 3;
                const int jl = cell & 7;
                cp_async16(xwsm + cell * 16,
                           g_XW + ((size_t)t * NB + b) * Z4 + (size_t)(n0 + jl * 4));
            }
        }
        CP_COMMIT();
        load_a_ops(1, 1);
        CP_COMMIT();

        for (int ch = 0; ch < 8; ch++) {
            if (ch < 7) asm volatile("cp.async.wait_group 1;" ::: "memory");
            else        asm volatile("cp.async.wait_group 0;" ::: "memory");
            __syncthreads();
            if (ch + 2 < 8) { load_a_ops(ch + 2, (ch + 2) % A_BUFS); CP_COMMIT(); }

            const uint32_t ab = ab0 + (ch % A_BUFS) * A_CHUNK;

            #pragma unroll
            for (int kk = 0; kk < 8; kk++) {
                const int sub = kk >> 2;
                const int k4  = kk & 3;
                uint32_t aoff = (uint32_t)((mw * 16 + lrow) * 128 + k4 * 32 + lcolb);
                uint32_t aaddr = ab + sub * 8192 + (aoff ^ ((aoff >> 3) & 0x70));
                uint32_t a0, a1, a2, a3;
                ldsm_x4(a0, a1, a2, a3, aaddr);

                const int bch = ch * 2 + sub;
                uint32_t boff = (uint32_t)((nw * 16 + lrow) * 128 + k4 * 32 + lcolb);
                uint32_t bsw  = boff ^ ((boff >> 3) & 0x70);
                uint32_t b0, b1, b2, b3, d0, d1, d2, d3;
                ldsm_x4(b0, b1, b2, b3, tb + bch * 4096 + bsw);
                ldsm_x4(d0, d1, d2, d3, tb + (16 + bch) * 4096 + bsw);

                mma_f16(c[0][0], a0, a1, a2, a3, b0, b2);
                mma_f16(c[0][1], a0, a1, a2, a3, b1, b3);
                mma_f16(c[1][0], a0, a1, a2, a3, d0, d2);
                mma_f16(c[1][1], a0, a1, a2, a3, d1, d3);
            }
        }
        __syncthreads();

        // epilogue -> smem z
        #pragma unroll
        for (int h = 0; h < 2; h++) {
            const int row = mw * 16 + (lane >> 2);
            const int col = nw * 16 + h * 8 + (lane & 3) * 2;
            zbuf[row * 33 + col]           = c[0][h][0] + c[1][h][0];
            zbuf[row * 33 + col + 1]       = c[0][h][1] + c[1][h][1];
            zbuf[(row + 8) * 33 + col]     = c[0][h][2] + c[1][h][2];
            zbuf[(row + 8) * 33 + col + 1] = c[0][h][3] + c[1][h][3];
        }
        __syncthreads();

        // block-local cell update
        __half* hw = g_H2[rb ^ 1];
        const __half* hr = g_H2[rb];
        #pragma unroll
        for (int r = 0; r < 2; r++) {
            const int cell = r * 256 + tid;
            const int b  = cell >> 3;
            const int jl = cell & 7;
            const int j  = j0 + jl;

            float4 xw4 = *reinterpret_cast<const float4*>(xws + cell * 4);
            const float zi = xw4.x + zbuf[b * 33 + jl * 4 + 0] + sbias[jl * 4 + 0];
            const float zf = xw4.y + zbuf[b * 33 + jl * 4 + 1] + sbias[jl * 4 + 1];
            const float zg = xw4.z + zbuf[b * 33 + jl * 4 + 2] + sbias[jl * 4 + 2];
            const float zo = xw4.w + zbuf[b * 33 + jl * 4 + 3] + sbias[jl * 4 + 3];

            const float si = fsigmoid(zi);
            const float sf = fsigmoid(zf);
            const float so = fsigmoid(zo);
            const float cn = sf * cs[cell] + si * ftanh(zg);
            const float hn = so * ftanh(cn);
            const int xv = x[b * NT + t];
            if (xv != 0) {
                cs[cell] = cn;
                hw[b * RNN + j] = __float2half_rn(hn);
            } else {
                hw[b * RNN + j] = hr[b * RNN + j];
            }
            if (xv == 2) pooled_s[cell] += hn;
        }

        // ---- fence-free grid barrier (acq_rel atomics, grid.sync pattern) ----
        epoch++;
        __syncthreads();
        if (tid == 0) {
            unsigned old;
            asm volatile("atom.acq_rel.gpu.global.add.u32 %0, [%1], %2;"
                         : "=r"(old) : "l"(&g_arrive), "r"(1u) : "memory");
            if (old == 127u) {
                g_arrive = 0;
                asm volatile("st.release.gpu.global.s32 [%0], %1;"
                             :: "l"(&g_release), "r"(epoch) : "memory");
            } else {
                int v;
                do {
                    asm volatile("ld.acquire.gpu.global.s32 %0, [%1];"
                                 : "=r"(v) : "l"(&g_release) : "memory");
                } while (v < epoch);
            }
        }
        __syncthreads();

        rb ^= 1;
    }

    // write pooled out
    #pragma unroll
    for (int r = 0; r < 2; r++) {
        const int cell = r * 256 + tid;
        const int b  = cell >> 3;
        const int jl = cell & 7;
        g_pooled[b * RNN + j0 + jl] = pooled_s[cell];
    }
}

// ---------------- head (precise math; errors here don't damp) --------------
__global__ __launch_bounds__(128) void head_kernel(const float* __restrict__ W1,
                                                   const float* __restrict__ b1,
                                                   const float* __restrict__ W2,
                                                   const float* __restrict__ b2,
                                                   const float* __restrict__ Wc,
                                                   const float* __restrict__ bc,
                                                   float* __restrict__ out) {
    const int b = blockIdx.x;
    const int tid = threadIdx.x;
    __shared__ float sp[RNN];
    __shared__ float h1s[HIDN];
    __shared__ float h2s[HIDN];
    __shared__ float lg[NLAB];

    for (int k = tid; k < RNN; k += 128) sp[k] = g_pooled[(size_t)b * RNN + k];
    __syncthreads();

    float a = b1[tid];
    for (int k = 0; k < RNN; k++) a += sp[k] * W1[(size_t)k * HIDN + tid];
    h1s[tid] = fmaxf(a, 0.f);
    __syncthreads();

    float a2 = b2[tid];
    for (int k = 0; k < HIDN; k++) a2 += h1s[k] * W2[(size_t)k * HIDN + tid];
    h2s[tid] = fmaxf(a2, 0.f);
    __syncthreads();

    if (tid < NLAB) {
        float l = bc[tid];
        for (int k = 0; k < HIDN; k++) l += h2s[k] * Wc[(size_t)k * NLAB + tid];
        lg[tid] = l;
    }
    __syncthreads();
    if (tid == 0) {
        const float mx = fmaxf(fmaxf(lg[0], lg[1]), fmaxf(lg[2], lg[3]));
        const float e0 = expf(lg[0] - mx), e1 = expf(lg[1] - mx);
        const float e2 = expf(lg[2] - mx), e3 = expf(lg[3] - mx);
        const float sden = e0 + e1 + e2 + e3;
        out[b * 4 + 0] = e0 / sden; out[b * 4 + 1] = e1 / sden;
        out[b * 4 + 2] = e2 / sden; out[b * 4 + 3] = e3 / sden;
    }
}

// ---------------- launcher -------------------------------------------------
extern "C" void kernel_launch(void* const* d_in, const int* in_sizes, int n_in,
                              void* d_out, int out_size) {
    const int*   x    = (const int*)d_in[0];
    const float* emb  = (const float*)d_in[1];
    const float* W    = (const float*)d_in[2];
    const float* U    = (const float*)d_in[3];
    const float* bias = (const float*)d_in[4];
    const float* W1   = (const float*)d_in[5];
    const float* b1   = (const float*)d_in[6];
    const float* W2   = (const float*)d_in[7];
    const float* b2   = (const float*)d_in[8];
    const float* Wc   = (const float*)d_in[9];
    const float* bc   = (const float*)d_in[10];
    float* out = (float*)d_out;

    cudaFuncSetAttribute(xw_mma_kernel, cudaFuncAttributeMaxDynamicSharedMemorySize, XW_SMEM);
    cudaFuncSetAttribute(rnn_persist, cudaFuncAttributeMaxDynamicSharedMemorySize, RNN_SMEM);

    prep_kernel<<<1, 256>>>(x);
    zero_kernel<<<256, 256>>>();
    esplit_kernel<<<(VOCAB * EMBD) / 256, 256>>>(emb);
    upack_kernel<<<dim3(RNN / 64, Z4 / 64), 256>>>(U);
    wpack_kernel<<<dim3(EMBD / 64, Z4 / 64), 256>>>(W);
    xw_mma_kernel<<<dim3(32, NT / 2), 256, XW_SMEM>>>(x);
    rnn_persist<<<128, 256, RNN_SMEM>>>(x, bias);
    head_kernel<<<NB, 128>>>(W1, b1, W2, b2, Wc, bc, out);
}